// round 1
// baseline (speedup 1.0000x reference)
#include <cuda_runtime.h>
#include <math.h>

#define GMAX 100000

// Scratch (static __device__ arrays: allocation-free)
__device__ float g_segsum[(size_t)GMAX * 256];
__device__ float g_segcnt[GMAX];

__device__ __forceinline__ float tf32r(float x){
    unsigned u; asm("cvt.rna.tf32.f32 %0, %1;" : "=r"(u) : "f"(x));
    return __uint_as_float(u);
}
__device__ __forceinline__ float gelu_exact(float x){
    return 0.5f * x * (1.0f + erff(x * 0.7071067811865475f));
}
__device__ __forceinline__ void mma8(float* c, const unsigned* a, unsigned b0, unsigned b1){
    asm volatile(
        "mma.sync.aligned.m16n8k8.row.col.f32.tf32.tf32.f32 "
        "{%0,%1,%2,%3},{%4,%5,%6,%7},{%8,%9},{%0,%1,%2,%3};\n"
        : "+f"(c[0]), "+f"(c[1]), "+f"(c[2]), "+f"(c[3])
        : "r"(a[0]), "r"(a[1]), "r"(a[2]), "r"(a[3]), "r"(b0), "r"(b1));
}

// Resident-A tf32 GEMM: accum C[rows x 256] += A[rows, 16*nchunk] @ W[16*nchunk, 256]
// A in smem (pitch APITCH, tf32-rounded). W streamed from gmem, double-buffered,
// smem pitch 264 (conflict-free for the m16n8k8 B-fragment pattern).
template<int APITCH, int NT>
__device__ __forceinline__ void gemm_resA(
    const float* __restrict__ Asm, const float* __restrict__ Wg,
    float* Wsb, float c[2][8][4], int nchunk,
    int row0, int col0, int lane, int tid)
{
    constexpr int F4 = 1024 / NT;  // float4 loads per thread per 16x256 chunk
    // prefetch chunk 0
    #pragma unroll
    for (int q = 0; q < F4; q++){
        int i = tid + q*NT;
        int k = i >> 6, n4 = i & 63;
        float4 v = *(const float4*)(Wg + ((size_t)k << 8) + (n4 << 2));
        *(float4*)(Wsb + k*264 + (n4 << 2)) =
            make_float4(tf32r(v.x), tf32r(v.y), tf32r(v.z), tf32r(v.w));
    }
    __syncthreads();
    for (int ch = 0; ch < nchunk; ch++){
        float4 nxt[F4];
        bool hn = (ch + 1) < nchunk;
        if (hn){
            #pragma unroll
            for (int q = 0; q < F4; q++){
                int i = tid + q*NT;
                int k = i >> 6, n4 = i & 63;
                nxt[q] = *(const float4*)(Wg + ((size_t)((ch+1)*16 + k) << 8) + (n4 << 2));
            }
        }
        const float* Wc = Wsb + (ch & 1) * (16*264);
        const int kb = ch * 16;
        #pragma unroll
        for (int ks = 0; ks < 16; ks += 8){
            unsigned a[2][4];
            #pragma unroll
            for (int mm = 0; mm < 2; mm++){
                const float* ap = Asm + (row0 + mm*16 + (lane >> 2))*APITCH + kb + ks + (lane & 3);
                a[mm][0] = __float_as_uint(ap[0]);
                a[mm][1] = __float_as_uint(ap[8*APITCH]);
                a[mm][2] = __float_as_uint(ap[4]);
                a[mm][3] = __float_as_uint(ap[8*APITCH + 4]);
            }
            #pragma unroll
            for (int nn = 0; nn < 8; nn++){
                const float* bp = Wc + (ks + (lane & 3))*264 + col0 + nn*8 + (lane >> 2);
                unsigned b0 = __float_as_uint(bp[0]);
                unsigned b1 = __float_as_uint(bp[4*264]);
                mma8(c[0][nn], a[0], b0, b1);
                mma8(c[1][nn], a[1], b0, b1);
            }
        }
        if (hn){
            float* Wn = Wsb + ((ch + 1) & 1) * (16*264);
            #pragma unroll
            for (int q = 0; q < F4; q++){
                int i = tid + q*NT;
                int k = i >> 6, n4 = i & 63;
                *(float4*)(Wn + k*264 + (n4 << 2)) =
                    make_float4(tf32r(nxt[q].x), tf32r(nxt[q].y), tf32r(nxt[q].z), tf32r(nxt[q].w));
            }
        }
        __syncthreads();
    }
}

// ---------------------------------------------------------------------------
// Kernel 0: zero the segment scratch
// ---------------------------------------------------------------------------
__global__ void zero_kernel(int G){
    size_t total  = (size_t)G * 256;
    size_t stride = (size_t)gridDim.x * blockDim.x;
    for (size_t i = (size_t)blockIdx.x * blockDim.x + threadIdx.x; i < total; i += stride)
        g_segsum[i] = 0.f;
    for (size_t i = (size_t)blockIdx.x * blockDim.x + threadIdx.x; i < (size_t)G; i += stride)
        g_segcnt[i] = 0.f;
}

// ---------------------------------------------------------------------------
// Kernel 1: fused node MLP (2 layers, exact GELU) + sorted-segment accumulate
// 512 threads, 128-row tile, warp grid 4x4, warp tile 32x64
// ---------------------------------------------------------------------------
// smem floats: Xb 2*128*20=5120 | H1s 128*260=33280 | Ws 2*16*264=8448 | b1s 256 | b2s 256 | segs 128(int)
#define NODE_SMEM_BYTES ((5120 + 33280 + 8448 + 256 + 256) * 4 + 128 * 4)

__global__ void __launch_bounds__(512, 1)
node_kernel(const float* __restrict__ hf, const float* __restrict__ sfeat,
            const float* __restrict__ W1, const float* __restrict__ b1,
            const float* __restrict__ W2, const float* __restrict__ b2,
            const int* __restrict__ seg, int N)
{
    extern __shared__ float sm[];
    float* Xb  = sm;                // 2 x [128 x 20]  (layer-1 A chunks, tf32)
    float* H1s = Xb + 5120;         // [128 x 260]
    float* Ws  = H1s + 33280;       // 2 x [16 x 264]
    float* b1s = Ws + 8448;         // 256
    float* b2s = b1s + 256;         // 256
    int*   segs = (int*)(b2s + 256);// 128

    const int tid  = threadIdx.x;
    const int lane = tid & 31;
    const int warp = tid >> 5;
    const int row0 = (warp & 3) * 32;
    const int col0 = (warp >> 2) * 64;
    const int r0   = blockIdx.x * 128;

    if (tid < 256){ b1s[tid] = b1[tid]; b2s[tid] = b2[tid]; }
    if (tid >= 256 && tid < 384){
        int r = r0 + tid - 256;
        segs[tid - 256] = (r < N) ? seg[r] : -1;
    }

    // prefetch chunk 0 of X (h cols 0..15) and W1
    {
        int r = tid >> 2, c4 = tid & 3;
        int gr = r0 + r;
        float4 v = make_float4(0.f, 0.f, 0.f, 0.f);
        if (gr < N) v = *(const float4*)(hf + (size_t)gr*256 + (c4 << 2));
        *(float4*)(Xb + r*20 + (c4 << 2)) =
            make_float4(tf32r(v.x), tf32r(v.y), tf32r(v.z), tf32r(v.w));
        #pragma unroll
        for (int q = 0; q < 2; q++){
            int j = tid + q*512;
            int k = j >> 6, n4 = j & 63;
            float4 w = *(const float4*)(W1 + ((size_t)k << 8) + (n4 << 2));
            *(float4*)(Ws + k*264 + (n4 << 2)) =
                make_float4(tf32r(w.x), tf32r(w.y), tf32r(w.z), tf32r(w.w));
        }
    }
    __syncthreads();

    float c[2][8][4];
    #pragma unroll
    for (int mm = 0; mm < 2; mm++)
        #pragma unroll
        for (int nn = 0; nn < 8; nn++)
            #pragma unroll
            for (int q = 0; q < 4; q++) c[mm][nn][q] = 0.f;

    // ---- layer 1: K = 272 (17 chunks of 16), X & W double-buffered ----
    for (int ch = 0; ch < 17; ch++){
        float4 nw[2], nx;
        bool hn = (ch + 1) < 17;
        if (hn){
            int k0n = (ch + 1) * 16;
            int r = tid >> 2, c4 = tid & 3;
            int gr = r0 + r;
            nx = make_float4(0.f, 0.f, 0.f, 0.f);
            if (gr < N){
                if (k0n < 256) nx = *(const float4*)(hf + (size_t)gr*256 + k0n + (c4 << 2));
                else           nx = *(const float4*)(sfeat + (size_t)gr*16 + (c4 << 2));
            }
            #pragma unroll
            for (int q = 0; q < 2; q++){
                int j = tid + q*512;
                int k = j >> 6, n4 = j & 63;
                nw[q] = *(const float4*)(W1 + ((size_t)(k0n + k) << 8) + (n4 << 2));
            }
        }
        const float* Wc = Ws + (ch & 1) * (16*264);
        const float* Xc = Xb + (ch & 1) * (128*20);
        #pragma unroll
        for (int ks = 0; ks < 16; ks += 8){
            unsigned a[2][4];
            #pragma unroll
            for (int mm = 0; mm < 2; mm++){
                const float* ap = Xc + (row0 + mm*16 + (lane >> 2))*20 + ks + (lane & 3);
                a[mm][0] = __float_as_uint(ap[0]);
                a[mm][1] = __float_as_uint(ap[8*20]);
                a[mm][2] = __float_as_uint(ap[4]);
                a[mm][3] = __float_as_uint(ap[8*20 + 4]);
            }
            #pragma unroll
            for (int nn = 0; nn < 8; nn++){
                const float* bp = Wc + (ks + (lane & 3))*264 + col0 + nn*8 + (lane >> 2);
                unsigned b0 = __float_as_uint(bp[0]);
                unsigned b1v = __float_as_uint(bp[4*264]);
                mma8(c[0][nn], a[0], b0, b1v);
                mma8(c[1][nn], a[1], b0, b1v);
            }
        }
        if (hn){
            float* Wn = Ws + ((ch + 1) & 1) * (16*264);
            float* Xn = Xb + ((ch + 1) & 1) * (128*20);
            {
                int r = tid >> 2, c4 = tid & 3;
                *(float4*)(Xn + r*20 + (c4 << 2)) =
                    make_float4(tf32r(nx.x), tf32r(nx.y), tf32r(nx.z), tf32r(nx.w));
            }
            #pragma unroll
            for (int q = 0; q < 2; q++){
                int j = tid + q*512;
                int k = j >> 6, n4 = j & 63;
                *(float4*)(Wn + k*264 + (n4 << 2)) =
                    make_float4(tf32r(nw[q].x), tf32r(nw[q].y), tf32r(nw[q].z), tf32r(nw[q].w));
            }
        }
        __syncthreads();
    }

    // epilogue layer 1: gelu(c + b1) -> H1s (tf32-rounded for layer-2 A)
    #pragma unroll
    for (int mm = 0; mm < 2; mm++){
        #pragma unroll
        for (int nn = 0; nn < 8; nn++){
            int rr = row0 + mm*16 + (lane >> 2);
            int cc = col0 + nn*8 + 2*(lane & 3);
            float* dst = H1s + rr*260 + cc;
            float bb0 = b1s[cc], bb1 = b1s[cc + 1];
            dst[0]         = tf32r(gelu_exact(c[mm][nn][0] + bb0));
            dst[1]         = tf32r(gelu_exact(c[mm][nn][1] + bb1));
            dst[8*260]     = tf32r(gelu_exact(c[mm][nn][2] + bb0));
            dst[8*260 + 1] = tf32r(gelu_exact(c[mm][nn][3] + bb1));
            #pragma unroll
            for (int q = 0; q < 4; q++) c[mm][nn][q] = 0.f;
        }
    }
    // gemm_resA begins with prefetch (Ws only) then __syncthreads, which
    // orders the H1s writes above before any H1s reads.

    // ---- layer 2: K = 256 ----
    gemm_resA<260, 512>(H1s, W2, Ws, c, 16, row0, col0, lane, tid);

    // epilogue layer 2: Y = c + b2 -> H1s (fp32). Safe: loop ended with barrier.
    #pragma unroll
    for (int mm = 0; mm < 2; mm++){
        #pragma unroll
        for (int nn = 0; nn < 8; nn++){
            int rr = row0 + mm*16 + (lane >> 2);
            int cc = col0 + nn*8 + 2*(lane & 3);
            float* dst = H1s + rr*260 + cc;
            float bb0 = b2s[cc], bb1 = b2s[cc + 1];
            dst[0]         = c[mm][nn][0] + bb0;
            dst[1]         = c[mm][nn][1] + bb1;
            dst[8*260]     = c[mm][nn][2] + bb0;
            dst[8*260 + 1] = c[mm][nn][3] + bb1;
        }
    }
    __syncthreads();

    // segment accumulate: 512 threads = 256 cols x 2 row-halves.
    // segment_ids are sorted -> run-length reduce in-tile, flush per run.
    {
        int col  = tid & 255;
        int half = tid >> 8;
        int rbeg = half * 64, rend = rbeg + 64;
        float acc = 0.f; int cur = -1;
        for (int r = rbeg; r < rend; r++){
            int s = segs[r];
            if (s != cur){
                if (cur >= 0) atomicAdd(&g_segsum[(size_t)cur*256 + col], acc);
                acc = 0.f; cur = s;
            }
            if (s >= 0) acc += H1s[r*260 + col];
        }
        if (cur >= 0) atomicAdd(&g_segsum[(size_t)cur*256 + col], acc);

        if (col == 0){  // counts: one thread per half
            float cnt = 0.f; int cu = -1;
            for (int r = rbeg; r < rend; r++){
                int s = segs[r];
                if (s != cu){
                    if (cu >= 0) atomicAdd(&g_segcnt[cu], cnt);
                    cnt = 0.f; cu = s;
                }
                if (s >= 0) cnt += 1.f;
            }
            if (cu >= 0) atomicAdd(&g_segcnt[cu], cnt);
        }
    }
}

// ---------------------------------------------------------------------------
// Kernel 2: head — mean, GEMM(Wc1)+GELU (tf32 mma), GEMM(Wc2)+bias (FFMA)
// 256 threads, 64-group tile, warp grid 2x4
// ---------------------------------------------------------------------------
// smem floats: Xs 16640 | Hs 16640 | Ws 8448 | bc1s 256 | w2s 2560 | bc2s 16 | cnts 64
#define HEAD_SMEM_BYTES ((16640 + 16640 + 8448 + 256 + 2560 + 16 + 64) * 4)

__global__ void __launch_bounds__(256, 1)
head_kernel(const float* __restrict__ Wc1, const float* __restrict__ bc1,
            const float* __restrict__ Wc2, const float* __restrict__ bc2,
            float* __restrict__ out, int G)
{
    extern __shared__ float sm[];
    float* Xs   = sm;               // [64 x 260]
    float* Hs   = Xs + 16640;       // [64 x 260]
    float* Ws   = Hs + 16640;       // 2 x [16 x 264]
    float* bc1s = Ws + 8448;        // 256
    float* w2s  = bc1s + 256;       // 256 x 10
    float* bc2s = w2s + 2560;       // 16
    float* cnts = bc2s + 16;        // 64

    const int tid  = threadIdx.x;
    const int lane = tid & 31;
    const int warp = tid >> 5;
    const int row0 = (warp & 1) * 32;
    const int col0 = (warp >> 1) * 64;
    const int g0   = blockIdx.x * 64;

    bc1s[tid] = bc1[tid];
    for (int i = tid; i < 2560; i += 256) w2s[i] = Wc2[i];
    if (tid < 10) bc2s[tid] = bc2[tid];
    if (tid < 64){
        int g = g0 + tid;
        float cc = (g < G) ? g_segcnt[g] : 1.f;
        cnts[tid] = fmaxf(cc, 1.f);
    }
    __syncthreads();

    // grouped = segsum / count, tf32-rounded, into Xs
    for (int i = tid; i < 64*64; i += 256){
        int r = i >> 6, c4 = i & 63;
        int g = g0 + r;
        float4 v = make_float4(0.f, 0.f, 0.f, 0.f);
        if (g < G){
            v = *(const float4*)(g_segsum + (size_t)g*256 + (c4 << 2));
            float inv = 1.f / cnts[r];
            v.x *= inv; v.y *= inv; v.z *= inv; v.w *= inv;
        }
        *(float4*)(Xs + r*260 + (c4 << 2)) =
            make_float4(tf32r(v.x), tf32r(v.y), tf32r(v.z), tf32r(v.w));
    }
    // gemm_resA's internal barrier (after its W prefetch) orders Xs writes.

    float c[2][8][4];
    #pragma unroll
    for (int mm = 0; mm < 2; mm++)
        #pragma unroll
        for (int nn = 0; nn < 8; nn++)
            #pragma unroll
            for (int q = 0; q < 4; q++) c[mm][nn][q] = 0.f;

    gemm_resA<260, 256>(Xs, Wc1, Ws, c, 16, row0, col0, lane, tid);

    // epilogue: Hs = gelu(c + bc1)  (fp32)
    #pragma unroll
    for (int mm = 0; mm < 2; mm++){
        #pragma unroll
        for (int nn = 0; nn < 8; nn++){
            int rr = row0 + mm*16 + (lane >> 2);
            int cc = col0 + nn*8 + 2*(lane & 3);
            float* dst = Hs + rr*260 + cc;
            float bb0 = bc1s[cc], bb1 = bc1s[cc + 1];
            dst[0]         = gelu_exact(c[mm][nn][0] + bb0);
            dst[1]         = gelu_exact(c[mm][nn][1] + bb1);
            dst[8*260]     = gelu_exact(c[mm][nn][2] + bb0);
            dst[8*260 + 1] = gelu_exact(c[mm][nn][3] + bb1);
        }
    }
    __syncthreads();

    // final small GEMM: out[64,10] = Hs[64,256] @ Wc2[256,10] + bc2 (FFMA)
    for (int idx = tid; idx < 640; idx += 256){
        int r = idx / 10, cl = idx - r*10;
        float acc = bc2s[cl];
        const float* hp = Hs + r*260;
        #pragma unroll 8
        for (int k = 0; k < 256; k++) acc += hp[k] * w2s[k*10 + cl];
        int g = g0 + r;
        if (g < G) out[(size_t)g*10 + cl] = acc;
    }
}

// ---------------------------------------------------------------------------
extern "C" void kernel_launch(void* const* d_in, const int* in_sizes, int n_in,
                              void* d_out, int out_size)
{
    const float* hf   = (const float*)d_in[0];
    const float* sf   = (const float*)d_in[1];
    const float* W1   = (const float*)d_in[2];
    const float* b1   = (const float*)d_in[3];
    const float* W2   = (const float*)d_in[4];
    const float* b2   = (const float*)d_in[5];
    const float* Wc1  = (const float*)d_in[6];
    const float* bc1  = (const float*)d_in[7];
    const float* Wc2  = (const float*)d_in[8];
    const float* bc2  = (const float*)d_in[9];
    const int*   seg  = (const int*)d_in[10];

    int N = in_sizes[0] / 256;   // h is [N, 256]
    int G = out_size / 10;       // out is [G, 10]

    cudaFuncSetAttribute(node_kernel, cudaFuncAttributeMaxDynamicSharedMemorySize, NODE_SMEM_BYTES);
    cudaFuncSetAttribute(head_kernel, cudaFuncAttributeMaxDynamicSharedMemorySize, HEAD_SMEM_BYTES);

    zero_kernel<<<1024, 256>>>(G);
    node_kernel<<<(N + 127) / 128, 512, NODE_SMEM_BYTES>>>(hf, sf, W1, b1, W2, b2, seg, N);
    head_kernel<<<(G + 63) / 64, 256, HEAD_SMEM_BYTES>>>(Wc1, bc1, Wc2, bc2, (float*)d_out, G);
}

// round 3
// speedup vs baseline: 1.0008x; 1.0008x over previous
#include <cuda_runtime.h>
#include <math.h>

#define GMAX 100000

// Scratch (static __device__ arrays: allocation-free)
__device__ float g_segsum[(size_t)GMAX * 256];
__device__ float g_segcnt[GMAX];

__device__ __forceinline__ float tf32r(float x){
    unsigned u; asm("cvt.rna.tf32.f32 %0, %1;" : "=r"(u) : "f"(x));
    return __uint_as_float(u);
}
__device__ __forceinline__ float gelu_exact(float x){
    return 0.5f * x * (1.0f + erff(x * 0.7071067811865475f));
}
__device__ __forceinline__ void mma8(float* c, const unsigned* a, unsigned b0, unsigned b1){
    asm volatile(
        "mma.sync.aligned.m16n8k8.row.col.f32.tf32.tf32.f32 "
        "{%0,%1,%2,%3},{%4,%5,%6,%7},{%8,%9},{%0,%1,%2,%3};\n"
        : "+f"(c[0]), "+f"(c[1]), "+f"(c[2]), "+f"(c[3])
        : "r"(a[0]), "r"(a[1]), "r"(a[2]), "r"(a[3]), "r"(b0), "r"(b1));
}

// Resident-A tf32 GEMM: accum C[rows x 256] += A[rows, 16*nchunk] @ W[16*nchunk, 256]
// A in smem (pitch APITCH, tf32-rounded). W streamed from gmem, double-buffered,
// smem pitch 264 (conflict-free for the m16n8k8 B-fragment pattern).
template<int APITCH, int NT>
__device__ __forceinline__ void gemm_resA(
    const float* __restrict__ Asm, const float* __restrict__ Wg,
    float* Wsb, float c[2][8][4], int nchunk,
    int row0, int col0, int lane, int tid)
{
    constexpr int F4 = 1024 / NT;  // float4 loads per thread per 16x256 chunk
    // prefetch chunk 0
    #pragma unroll
    for (int q = 0; q < F4; q++){
        int i = tid + q*NT;
        int k = i >> 6, n4 = i & 63;
        float4 v = *(const float4*)(Wg + ((size_t)k << 8) + (n4 << 2));
        *(float4*)(Wsb + k*264 + (n4 << 2)) =
            make_float4(tf32r(v.x), tf32r(v.y), tf32r(v.z), tf32r(v.w));
    }
    __syncthreads();
    for (int ch = 0; ch < nchunk; ch++){
        float4 nxt[F4];
        bool hn = (ch + 1) < nchunk;
        if (hn){
            #pragma unroll
            for (int q = 0; q < F4; q++){
                int i = tid + q*NT;
                int k = i >> 6, n4 = i & 63;
                nxt[q] = *(const float4*)(Wg + ((size_t)((ch+1)*16 + k) << 8) + (n4 << 2));
            }
        }
        const float* Wc = Wsb + (ch & 1) * (16*264);
        const int kb = ch * 16;
        #pragma unroll
        for (int ks = 0; ks < 16; ks += 8){
            unsigned a[2][4];
            #pragma unroll
            for (int mm = 0; mm < 2; mm++){
                const float* ap = Asm + (row0 + mm*16 + (lane >> 2))*APITCH + kb + ks + (lane & 3);
                a[mm][0] = __float_as_uint(ap[0]);
                a[mm][1] = __float_as_uint(ap[8*APITCH]);
                a[mm][2] = __float_as_uint(ap[4]);
                a[mm][3] = __float_as_uint(ap[8*APITCH + 4]);
            }
            #pragma unroll
            for (int nn = 0; nn < 8; nn++){
                const float* bp = Wc + (ks + (lane & 3))*264 + col0 + nn*8 + (lane >> 2);
                unsigned b0 = __float_as_uint(bp[0]);
                unsigned b1 = __float_as_uint(bp[4*264]);
                mma8(c[0][nn], a[0], b0, b1);
                mma8(c[1][nn], a[1], b0, b1);
            }
        }
        if (hn){
            float* Wn = Wsb + ((ch + 1) & 1) * (16*264);
            #pragma unroll
            for (int q = 0; q < F4; q++){
                int i = tid + q*NT;
                int k = i >> 6, n4 = i & 63;
                *(float4*)(Wn + k*264 + (n4 << 2)) =
                    make_float4(tf32r(nxt[q].x), tf32r(nxt[q].y), tf32r(nxt[q].z), tf32r(nxt[q].w));
            }
        }
        __syncthreads();
    }
}

// ---------------------------------------------------------------------------
// Kernel 0: zero the segment scratch
// ---------------------------------------------------------------------------
__global__ void zero_kernel(int G){
    size_t total  = (size_t)G * 256;
    size_t stride = (size_t)gridDim.x * blockDim.x;
    for (size_t i = (size_t)blockIdx.x * blockDim.x + threadIdx.x; i < total; i += stride)
        g_segsum[i] = 0.f;
    for (size_t i = (size_t)blockIdx.x * blockDim.x + threadIdx.x; i < (size_t)G; i += stride)
        g_segcnt[i] = 0.f;
}

// ---------------------------------------------------------------------------
// Kernel 1: fused node MLP (2 layers, exact GELU) + sorted-segment accumulate
// 512 threads, 128-row tile, warp grid 4x4, warp tile 32x64
// ---------------------------------------------------------------------------
// smem floats: Xb 2*128*20=5120 | H1s 128*260=33280 | Ws 2*16*264=8448 | b1s 256 | b2s 256 | segs 128(int)
#define NODE_SMEM_BYTES ((5120 + 33280 + 8448 + 256 + 256) * 4 + 128 * 4)

__global__ void __launch_bounds__(512, 1)
node_kernel(const float* __restrict__ hf, const float* __restrict__ sfeat,
            const float* __restrict__ W1, const float* __restrict__ b1,
            const float* __restrict__ W2, const float* __restrict__ b2,
            const int* __restrict__ seg, int N)
{
    extern __shared__ float sm[];
    float* Xb  = sm;                // 2 x [128 x 20]  (layer-1 A chunks, tf32)
    float* H1s = Xb + 5120;         // [128 x 260]
    float* Ws  = H1s + 33280;       // 2 x [16 x 264]
    float* b1s = Ws + 8448;         // 256
    float* b2s = b1s + 256;         // 256
    int*   segs = (int*)(b2s + 256);// 128

    const int tid  = threadIdx.x;
    const int lane = tid & 31;
    const int warp = tid >> 5;
    const int row0 = (warp & 3) * 32;
    const int col0 = (warp >> 2) * 64;
    const int r0   = blockIdx.x * 128;

    if (tid < 256){ b1s[tid] = b1[tid]; b2s[tid] = b2[tid]; }
    if (tid >= 256 && tid < 384){
        int r = r0 + tid - 256;
        segs[tid - 256] = (r < N) ? seg[r] : -1;
    }

    // prefetch chunk 0 of X (h cols 0..15) and W1
    {
        int r = tid >> 2, c4 = tid & 3;
        int gr = r0 + r;
        float4 v = make_float4(0.f, 0.f, 0.f, 0.f);
        if (gr < N) v = *(const float4*)(hf + (size_t)gr*256 + (c4 << 2));
        *(float4*)(Xb + r*20 + (c4 << 2)) =
            make_float4(tf32r(v.x), tf32r(v.y), tf32r(v.z), tf32r(v.w));
        #pragma unroll
        for (int q = 0; q < 2; q++){
            int j = tid + q*512;
            int k = j >> 6, n4 = j & 63;
            float4 w = *(const float4*)(W1 + ((size_t)k << 8) + (n4 << 2));
            *(float4*)(Ws + k*264 + (n4 << 2)) =
                make_float4(tf32r(w.x), tf32r(w.y), tf32r(w.z), tf32r(w.w));
        }
    }
    __syncthreads();

    float c[2][8][4];
    #pragma unroll
    for (int mm = 0; mm < 2; mm++)
        #pragma unroll
        for (int nn = 0; nn < 8; nn++)
            #pragma unroll
            for (int q = 0; q < 4; q++) c[mm][nn][q] = 0.f;

    // ---- layer 1: K = 272 (17 chunks of 16), X & W double-buffered ----
    for (int ch = 0; ch < 17; ch++){
        float4 nw[2], nx;
        bool hn = (ch + 1) < 17;
        if (hn){
            int k0n = (ch + 1) * 16;
            int r = tid >> 2, c4 = tid & 3;
            int gr = r0 + r;
            nx = make_float4(0.f, 0.f, 0.f, 0.f);
            if (gr < N){
                if (k0n < 256) nx = *(const float4*)(hf + (size_t)gr*256 + k0n + (c4 << 2));
                else           nx = *(const float4*)(sfeat + (size_t)gr*16 + (c4 << 2));
            }
            #pragma unroll
            for (int q = 0; q < 2; q++){
                int j = tid + q*512;
                int k = j >> 6, n4 = j & 63;
                nw[q] = *(const float4*)(W1 + ((size_t)(k0n + k) << 8) + (n4 << 2));
            }
        }
        const float* Wc = Ws + (ch & 1) * (16*264);
        const float* Xc = Xb + (ch & 1) * (128*20);
        #pragma unroll
        for (int ks = 0; ks < 16; ks += 8){
            unsigned a[2][4];
            #pragma unroll
            for (int mm = 0; mm < 2; mm++){
                const float* ap = Xc + (row0 + mm*16 + (lane >> 2))*20 + ks + (lane & 3);
                a[mm][0] = __float_as_uint(ap[0]);
                a[mm][1] = __float_as_uint(ap[8*20]);
                a[mm][2] = __float_as_uint(ap[4]);
                a[mm][3] = __float_as_uint(ap[8*20 + 4]);
            }
            #pragma unroll
            for (int nn = 0; nn < 8; nn++){
                const float* bp = Wc + (ks + (lane & 3))*264 + col0 + nn*8 + (lane >> 2);
                unsigned b0 = __float_as_uint(bp[0]);
                unsigned b1v = __float_as_uint(bp[4*264]);
                mma8(c[0][nn], a[0], b0, b1v);
                mma8(c[1][nn], a[1], b0, b1v);
            }
        }
        if (hn){
            float* Wn = Ws + ((ch + 1) & 1) * (16*264);
            float* Xn = Xb + ((ch + 1) & 1) * (128*20);
            {
                int r = tid >> 2, c4 = tid & 3;
                *(float4*)(Xn + r*20 + (c4 << 2)) =
                    make_float4(tf32r(nx.x), tf32r(nx.y), tf32r(nx.z), tf32r(nx.w));
            }
            #pragma unroll
            for (int q = 0; q < 2; q++){
                int j = tid + q*512;
                int k = j >> 6, n4 = j & 63;
                *(float4*)(Wn + k*264 + (n4 << 2)) =
                    make_float4(tf32r(nw[q].x), tf32r(nw[q].y), tf32r(nw[q].z), tf32r(nw[q].w));
            }
        }
        __syncthreads();
    }

    // epilogue layer 1: gelu(c + b1) -> H1s (tf32-rounded for layer-2 A)
    #pragma unroll
    for (int mm = 0; mm < 2; mm++){
        #pragma unroll
        for (int nn = 0; nn < 8; nn++){
            int rr = row0 + mm*16 + (lane >> 2);
            int cc = col0 + nn*8 + 2*(lane & 3);
            float* dst = H1s + rr*260 + cc;
            float bb0 = b1s[cc], bb1 = b1s[cc + 1];
            dst[0]         = tf32r(gelu_exact(c[mm][nn][0] + bb0));
            dst[1]         = tf32r(gelu_exact(c[mm][nn][1] + bb1));
            dst[8*260]     = tf32r(gelu_exact(c[mm][nn][2] + bb0));
            dst[8*260 + 1] = tf32r(gelu_exact(c[mm][nn][3] + bb1));
            #pragma unroll
            for (int q = 0; q < 4; q++) c[mm][nn][q] = 0.f;
        }
    }
    // gemm_resA begins with prefetch (Ws only) then __syncthreads, which
    // orders the H1s writes above before any H1s reads.

    // ---- layer 2: K = 256 ----
    gemm_resA<260, 512>(H1s, W2, Ws, c, 16, row0, col0, lane, tid);

    // epilogue layer 2: Y = c + b2 -> H1s (fp32). Safe: loop ended with barrier.
    #pragma unroll
    for (int mm = 0; mm < 2; mm++){
        #pragma unroll
        for (int nn = 0; nn < 8; nn++){
            int rr = row0 + mm*16 + (lane >> 2);
            int cc = col0 + nn*8 + 2*(lane & 3);
            float* dst = H1s + rr*260 + cc;
            float bb0 = b2s[cc], bb1 = b2s[cc + 1];
            dst[0]         = c[mm][nn][0] + bb0;
            dst[1]         = c[mm][nn][1] + bb1;
            dst[8*260]     = c[mm][nn][2] + bb0;
            dst[8*260 + 1] = c[mm][nn][3] + bb1;
        }
    }
    __syncthreads();

    // segment accumulate: 512 threads = 256 cols x 2 row-halves.
    // segment_ids are sorted -> run-length reduce in-tile, flush per run.
    {
        int col  = tid & 255;
        int half = tid >> 8;
        int rbeg = half * 64, rend = rbeg + 64;
        float acc = 0.f; int cur = -1;
        for (int r = rbeg; r < rend; r++){
            int s = segs[r];
            if (s != cur){
                if (cur >= 0) atomicAdd(&g_segsum[(size_t)cur*256 + col], acc);
                acc = 0.f; cur = s;
            }
            if (s >= 0) acc += H1s[r*260 + col];
        }
        if (cur >= 0) atomicAdd(&g_segsum[(size_t)cur*256 + col], acc);

        if (col == 0){  // counts: one thread per half
            float cnt = 0.f; int cu = -1;
            for (int r = rbeg; r < rend; r++){
                int s = segs[r];
                if (s != cu){
                    if (cu >= 0) atomicAdd(&g_segcnt[cu], cnt);
                    cnt = 0.f; cu = s;
                }
                if (s >= 0) cnt += 1.f;
            }
            if (cu >= 0) atomicAdd(&g_segcnt[cu], cnt);
        }
    }
}

// ---------------------------------------------------------------------------
// Kernel 2: head — mean, GEMM(Wc1)+GELU (tf32 mma), GEMM(Wc2)+bias (FFMA)
// 256 threads, 64-group tile, warp grid 2x4
// ---------------------------------------------------------------------------
// smem floats: Xs 16640 | Hs 16640 | Ws 8448 | bc1s 256 | w2s 2560 | bc2s 16 | cnts 64
#define HEAD_SMEM_BYTES ((16640 + 16640 + 8448 + 256 + 2560 + 16 + 64) * 4)

__global__ void __launch_bounds__(256, 1)
head_kernel(const float* __restrict__ Wc1, const float* __restrict__ bc1,
            const float* __restrict__ Wc2, const float* __restrict__ bc2,
            float* __restrict__ out, int G)
{
    extern __shared__ float sm[];
    float* Xs   = sm;               // [64 x 260]
    float* Hs   = Xs + 16640;       // [64 x 260]
    float* Ws   = Hs + 16640;       // 2 x [16 x 264]
    float* bc1s = Ws + 8448;        // 256
    float* w2s  = bc1s + 256;       // 256 x 10
    float* bc2s = w2s + 2560;       // 16
    float* cnts = bc2s + 16;        // 64

    const int tid  = threadIdx.x;
    const int lane = tid & 31;
    const int warp = tid >> 5;
    const int row0 = (warp & 1) * 32;
    const int col0 = (warp >> 1) * 64;
    const int g0   = blockIdx.x * 64;

    bc1s[tid] = bc1[tid];
    for (int i = tid; i < 2560; i += 256) w2s[i] = Wc2[i];
    if (tid < 10) bc2s[tid] = bc2[tid];
    if (tid < 64){
        int g = g0 + tid;
        float cc = (g < G) ? g_segcnt[g] : 1.f;
        cnts[tid] = fmaxf(cc, 1.f);
    }
    __syncthreads();

    // grouped = segsum / count, tf32-rounded, into Xs
    for (int i = tid; i < 64*64; i += 256){
        int r = i >> 6, c4 = i & 63;
        int g = g0 + r;
        float4 v = make_float4(0.f, 0.f, 0.f, 0.f);
        if (g < G){
            v = *(const float4*)(g_segsum + (size_t)g*256 + (c4 << 2));
            float inv = 1.f / cnts[r];
            v.x *= inv; v.y *= inv; v.z *= inv; v.w *= inv;
        }
        *(float4*)(Xs + r*260 + (c4 << 2)) =
            make_float4(tf32r(v.x), tf32r(v.y), tf32r(v.z), tf32r(v.w));
    }
    // gemm_resA's internal barrier (after its W prefetch) orders Xs writes.

    float c[2][8][4];
    #pragma unroll
    for (int mm = 0; mm < 2; mm++)
        #pragma unroll
        for (int nn = 0; nn < 8; nn++)
            #pragma unroll
            for (int q = 0; q < 4; q++) c[mm][nn][q] = 0.f;

    gemm_resA<260, 256>(Xs, Wc1, Ws, c, 16, row0, col0, lane, tid);

    // epilogue: Hs = gelu(c + bc1)  (fp32)
    #pragma unroll
    for (int mm = 0; mm < 2; mm++){
        #pragma unroll
        for (int nn = 0; nn < 8; nn++){
            int rr = row0 + mm*16 + (lane >> 2);
            int cc = col0 + nn*8 + 2*(lane & 3);
            float* dst = Hs + rr*260 + cc;
            float bb0 = bc1s[cc], bb1 = bc1s[cc + 1];
            dst[0]         = gelu_exact(c[mm][nn][0] + bb0);
            dst[1]         = gelu_exact(c[mm][nn][1] + bb1);
            dst[8*260]     = gelu_exact(c[mm][nn][2] + bb0);
            dst[8*260 + 1] = gelu_exact(c[mm][nn][3] + bb1);
        }
    }
    __syncthreads();

    // final small GEMM: out[64,10] = Hs[64,256] @ Wc2[256,10] + bc2 (FFMA)
    for (int idx = tid; idx < 640; idx += 256){
        int r = idx / 10, cl = idx - r*10;
        float acc = bc2s[cl];
        const float* hp = Hs + r*260;
        #pragma unroll 8
        for (int k = 0; k < 256; k++) acc += hp[k] * w2s[k*10 + cl];
        int g = g0 + r;
        if (g < G) out[(size_t)g*10 + cl] = acc;
    }
}

// ---------------------------------------------------------------------------
extern "C" void kernel_launch(void* const* d_in, const int* in_sizes, int n_in,
                              void* d_out, int out_size)
{
    const float* hf   = (const float*)d_in[0];
    const float* sf   = (const float*)d_in[1];
    const float* W1   = (const float*)d_in[2];
    const float* b1   = (const float*)d_in[3];
    const float* W2   = (const float*)d_in[4];
    const float* b2   = (const float*)d_in[5];
    const float* Wc1  = (const float*)d_in[6];
    const float* bc1  = (const float*)d_in[7];
    const float* Wc2  = (const float*)d_in[8];
    const float* bc2  = (const float*)d_in[9];
    const int*   seg  = (const int*)d_in[10];

    int N = in_sizes[0] / 256;   // h is [N, 256]
    int G = out_size / 10;       // out is [G, 10]

    cudaFuncSetAttribute(node_kernel, cudaFuncAttributeMaxDynamicSharedMemorySize, NODE_SMEM_BYTES);
    cudaFuncSetAttribute(head_kernel, cudaFuncAttributeMaxDynamicSharedMemorySize, HEAD_SMEM_BYTES);

    zero_kernel<<<1024, 256>>>(G);
    node_kernel<<<(N + 127) / 128, 512, NODE_SMEM_BYTES>>>(hf, sf, W1, b1, W2, b2, seg, N);
    head_kernel<<<(G + 63) / 64, 256, HEAD_SMEM_BYTES>>>(Wc1, bc1, Wc2, bc2, (float*)d_out, G);
}

// round 8
// speedup vs baseline: 1.1342x; 1.1333x over previous
#include <cuda_runtime.h>
#include <stdint.h>
#include <math.h>

#define GMAX 100000

// ---------------- static scratch ----------------
__device__ float g_segsum[(size_t)GMAX*256];
__device__ float g_segcnt[GMAX];
__device__ float g_W1p[36*2048];   // fragment-packed, tf32-rounded, K padded to 288
__device__ float g_W2p[32*2048];
__device__ float g_Wc1p[32*2048];

// ---------------- smem byte offsets (shared layout for node & head) ----------
#define OFF_H1   0          // 135168 B : H1 perm (128x264 f32) / W slots 0,1 (layer-1) / Y (128x260)
#define OFF_X0   135168     // X buf 0 (128x40 f32 = 20480) ; layer-2 W slot even
#define OFF_X1   155648     // X buf 1
#define OFF_WF   176128     // 32768 B : layer-2 W slot odd ; head: Wc2s copy
#define OFF_B1   208896     // 1024 B bias1
#define OFF_B2   209920     // 1024 B bias2
#define OFF_SEG  210944     // 512 B segs / invc
#define OFF_MB   211456     // mbarriers (2 x 8B)
#define SMB      212992

__device__ __forceinline__ float tf32r(float x){
    unsigned u; asm("cvt.rna.tf32.f32 %0, %1;" : "=r"(u) : "f"(x));
    return __uint_as_float(u);
}
__device__ __forceinline__ float gelu(float x){
    return 0.5f * x * (1.0f + erff(x * 0.70710678118654752f));
}
__device__ __forceinline__ void mma8(float* c, const unsigned* a, unsigned b0, unsigned b1){
    asm volatile(
        "mma.sync.aligned.m16n8k8.row.col.f32.tf32.tf32.f32 "
        "{%0,%1,%2,%3},{%4,%5,%6,%7},{%8,%9},{%0,%1,%2,%3};\n"
        : "+f"(c[0]), "+f"(c[1]), "+f"(c[2]), "+f"(c[3])
        : "r"(a[0]), "r"(a[1]), "r"(a[2]), "r"(a[3]), "r"(b0), "r"(b1));
}
__device__ __forceinline__ void bulkcp(uint32_t dst, const float* src, uint32_t bytes, uint32_t mbar){
    asm volatile("cp.async.bulk.shared::cluster.global.mbarrier::complete_tx::bytes [%0], [%1], %2, [%3];"
        :: "r"(dst), "l"(src), "r"(bytes), "r"(mbar) : "memory");
}
__device__ __forceinline__ uint32_t s2u(const void* p){
    uint32_t a; asm("{ .reg .u64 t; cvta.to.shared.u64 t, %1; cvt.u32.u64 %0, t; }" : "=r"(a) : "l"(p));
    return a;
}
#define MB_INIT(a,c)  asm volatile("mbarrier.init.shared.b64 [%0], %1;" :: "r"(a), "r"(c) : "memory")
#define MB_EXPECT(a,b) asm volatile("mbarrier.arrive.expect_tx.shared.b64 _, [%0], %1;" :: "r"(a), "r"(b) : "memory")
#define MB_WAIT(a,p) do{ uint32_t _m=(a); uint32_t _p=(p); uint32_t _d; \
    asm volatile("{\n\t.reg .pred p;\n\tmbarrier.try_wait.parity.acquire.cta.shared::cta.b64 p, [%1], %2;\n\tselp.b32 %0,1,0,p;\n\t}" \
        : "=r"(_d) : "r"(_m), "r"(_p) : "memory"); \
    if(!_d){ asm volatile("{\n\t.reg .pred P1;\nWL_%=:\n\tmbarrier.try_wait.parity.acquire.cta.shared::cta.b64 P1, [%0], %1, 0x989680;\n\t@P1 bra.uni WD_%=;\n\tbra.uni WL_%=;\nWD_%=:\n\t}" \
        :: "r"(_m), "r"(_p) : "memory"); } }while(0)

// perm position of k-offset j (0..7) inside an 8-float k8 block: [k0,k4,k1,k5,k2,k6,k3,k7]
__device__ __forceinline__ int permpos(int j){ return ((j & 3) << 1) | ((j & 4) >> 2); }

// ---------------------------------------------------------------------------
// prep: zero segsum, counts via binary search, fragment-pack weights
// B-pack: flat[(k8*16 + n>>4)*128 + ((n&7)*4 + (k&3))*4 + ((k&4)>>2) + ((n&8)>>2)]
// ---------------------------------------------------------------------------
__device__ __forceinline__ void packW(float* dst, const float* src, int Ktrue, int K8tot,
                                      int Ncols, size_t t0, size_t stride)
{
    size_t tot = (size_t)K8tot * 2048;
    for (size_t i = t0; i < tot; i += stride){
        int q  = (int)(i & 3);
        int L  = (int)((i >> 2) & 31);
        int cp = (int)((i >> 7) & 15);
        int k8 = (int)(i >> 11);
        int k = k8*8 + (L & 3) + ((q & 1) << 2);
        int n = cp*16 + (L >> 2) + ((q & 2) << 2);
        dst[i] = (k < Ktrue) ? tf32r(src[(size_t)k*Ncols + n]) : 0.f;
    }
}

__global__ void prep_kernel(const float* __restrict__ W1, const float* __restrict__ W2,
                            const float* __restrict__ Wc1,
                            const int* __restrict__ seg, int N, int G)
{
    size_t stride = (size_t)gridDim.x * blockDim.x;
    size_t t0 = (size_t)blockIdx.x * blockDim.x + threadIdx.x;
    float4* z = (float4*)g_segsum;
    for (size_t i = t0; i < (size_t)G*64; i += stride) z[i] = make_float4(0.f,0.f,0.f,0.f);
    for (size_t g = t0; g < (size_t)G; g += stride){
        int gi = (int)g;
        int lo = 0, hi = N;
        while (lo < hi){ int m = (lo+hi) >> 1; if (seg[m] < gi) lo = m+1; else hi = m; }
        int lb = lo; hi = N;
        while (lo < hi){ int m = (lo+hi) >> 1; if (seg[m] <= gi) lo = m+1; else hi = m; }
        g_segcnt[g] = (float)(lo - lb);
    }
    packW(g_W1p,  W1,  272, 36, 256, t0, stride);
    packW(g_W2p,  W2,  256, 32, 256, t0, stride);
    packW(g_Wc1p, Wc1, 256, 32, 256, t0, stride);
}

// ---------------------------------------------------------------------------
// shared compute step: one k8 (K=8) for the whole warp tile (64 rows x 64 cols)
// ---------------------------------------------------------------------------
__device__ __forceinline__ void kstep(const float* Ab, int PA, int k8off,
                                      const float* Wb, int k8, int row0, int cg,
                                      int lane, float c[4][8][4])
{
    unsigned a[4][4];
    #pragma unroll
    for (int mm = 0; mm < 4; mm++){
        const float* ap = Ab + (row0 + mm*16 + (lane >> 2))*PA + k8off + 2*(lane & 3);
        uint2 p = *(const uint2*)ap;
        uint2 q = *(const uint2*)(ap + 8*PA);
        a[mm][0] = p.x; a[mm][2] = p.y; a[mm][1] = q.x; a[mm][3] = q.y;
    }
    unsigned b[4][4];
    #pragma unroll
    for (int cp = 0; cp < 4; cp++){
        uint4 v = *(const uint4*)(Wb + ((k8*16 + cg*4 + cp)*128 + lane*4));
        b[cp][0] = v.x; b[cp][1] = v.y; b[cp][2] = v.z; b[cp][3] = v.w;
    }
    #pragma unroll
    for (int mm = 0; mm < 4; mm++){
        #pragma unroll
        for (int cp = 0; cp < 4; cp++){
            mma8(c[mm][cp*2],     a[mm], b[cp][0], b[cp][1]);
            mma8(c[mm][cp*2 + 1], a[mm], b[cp][2], b[cp][3]);
        }
    }
}

// X stage: thread covers row r = tid&127, k8 blocks {tid>>7, (tid>>7)+2}
__device__ __forceinline__ void node_ldx(float* xr, const float* hf, const float* sf,
                                         int r0, int N, int c, int tid)
{
    int r = tid & 127, k8a = tid >> 7;
    int gr = r0 + r;
    #pragma unroll
    for (int it = 0; it < 2; it++){
        int kg = c*32 + (k8a + it*2)*8;
        float4 v0 = make_float4(0.f,0.f,0.f,0.f), v1 = v0;
        if (gr < N){
            if (kg < 256){
                v0 = *(const float4*)(hf + (size_t)gr*256 + kg);
                v1 = *(const float4*)(hf + (size_t)gr*256 + kg + 4);
            } else if (kg < 272){
                v0 = *(const float4*)(sf + (size_t)gr*16 + (kg - 256));
                v1 = *(const float4*)(sf + (size_t)gr*16 + (kg - 252));
            }
        }
        float* x = xr + it*8;
        x[0]=v0.x; x[1]=v0.y; x[2]=v0.z; x[3]=v0.w;
        x[4]=v1.x; x[5]=v1.y; x[6]=v1.z; x[7]=v1.w;
    }
}
__device__ __forceinline__ void stage_stx(const float* xr, float* xb, int tid)
{
    int r = tid & 127, k8a = tid >> 7;
    #pragma unroll
    for (int it = 0; it < 2; it++){
        const float* x = xr + it*8;
        float* d = xb + r*40 + (k8a + it*2)*8;
        ((float4*)d)[0] = make_float4(tf32r(x[0]), tf32r(x[4]), tf32r(x[1]), tf32r(x[5]));
        ((float4*)d)[1] = make_float4(tf32r(x[2]), tf32r(x[6]), tf32r(x[3]), tf32r(x[7]));
    }
}

// ---------------------------------------------------------------------------
// node kernel: 256 thr, 8 warps (2 row-groups x 4 col-groups), tile 128 rows
// unified 17-chunk W pipeline: gc 0..8 layer-1 (K=288), gc 9..16 layer-2 (K=256)
// ---------------------------------------------------------------------------
__global__ void __launch_bounds__(256, 1)
node_kernel(const float* __restrict__ hf, const float* __restrict__ sf,
            const float* __restrict__ b1, const float* __restrict__ b2,
            const int* __restrict__ seg, int N)
{
    extern __shared__ float smraw[];
    char* sb = (char*)smraw;
    uint32_t B0 = s2u(sb);
    float* H1  = (float*)(sb + OFF_H1);     // perm layout pitch 264
    float* Ysm = (float*)(sb + OFF_H1);     // row-major pitch 260 (epilogue-2 overlay)
    float* b1s = (float*)(sb + OFF_B1);
    float* b2s = (float*)(sb + OFF_B2);
    int*  segs = (int*)(sb + OFF_SEG);
    const uint32_t MB = B0 + OFF_MB;

    int tid = threadIdx.x, lane = tid & 31, warp = tid >> 5;
    int row0 = (warp & 1) * 64, cg = warp >> 1;
    int col0 = cg * 64;
    int r0 = blockIdx.x * 128;

    b1s[tid] = b1[tid]; b2s[tid] = b2[tid];
    if (tid < 128){ int r = r0 + tid; segs[tid] = (r < N) ? seg[r] : -1; }
    if (tid == 0){ MB_INIT(MB, 1); MB_INIT(MB + 8, 1); }
    __syncthreads();

    float xr[16];
    node_ldx(xr, hf, sf, r0, N, 0, tid);

    float c[4][8][4];
    #pragma unroll
    for (int mm = 0; mm < 4; mm++)
        #pragma unroll
        for (int nn = 0; nn < 8; nn++)
            #pragma unroll
            for (int q = 0; q < 4; q++) c[mm][nn][q] = 0.f;

    if (tid == 0){  // kick chunk 0
        MB_EXPECT(MB, 32768u);
        bulkcp(B0 + OFF_H1, g_W1p, 32768, MB);
    }

    for (int gc = 0; gc < 17; gc++){
        int b = gc & 1;
        bool L1 = (gc < 9);
        if (L1){
            stage_stx(xr, (float*)(sb + (b ? OFF_X1 : OFF_X0)), tid);
            if (gc < 8) node_ldx(xr, hf, sf, r0, N, gc + 1, tid);
        }
        if (tid == 0 && gc < 16){
            int g2 = gc + 1, b2i = g2 & 1;
            uint32_t slot = (g2 < 9) ? (B0 + OFF_H1 + b2i*32768)
                                     : (B0 + (b2i ? OFF_WF : OFF_X0));
            const float* src = (g2 < 9) ? (g_W1p + g2*8192) : (g_W2p + (g2 - 9)*8192);
            MB_EXPECT(MB + b2i*8, 32768u);
            bulkcp(slot, src, 32768, MB + b2i*8);
        }
        __syncthreads();
        MB_WAIT(MB + b*8, (gc >> 1) & 1);

        const float* Wb = (const float*)(sb + ((gc < 9) ? (OFF_H1 + b*32768)
                                                        : (b ? OFF_WF : OFF_X0)));
        const float* Ab = L1 ? (const float*)(sb + (b ? OFF_X1 : OFF_X0)) : H1;
        int PA = L1 ? 40 : 264;
        int kbase = L1 ? 0 : (gc - 9)*4;
        #pragma unroll
        for (int k8 = 0; k8 < 4; k8++)
            kstep(Ab, PA, (kbase + k8)*8, Wb, k8, row0, cg, lane, c);
        __syncthreads();

        if (gc == 8){
            // epilogue-1: H1 = tf32(gelu(c + b1)), perm layout
            #pragma unroll
            for (int mm = 0; mm < 4; mm++){
                #pragma unroll
                for (int nn = 0; nn < 8; nn++){
                    int rr = row0 + mm*16 + (lane >> 2);
                    int cc = col0 + nn*8 + 2*(lane & 3);
                    int base = ((cc >> 3) << 3);
                    int p0 = base + permpos(cc & 7), p1 = base + permpos((cc + 1) & 7);
                    float bb0 = b1s[cc], bb1 = b1s[cc + 1];
                    H1[rr*264 + p0]       = tf32r(gelu(c[mm][nn][0] + bb0));
                    H1[rr*264 + p1]       = tf32r(gelu(c[mm][nn][1] + bb1));
                    H1[(rr + 8)*264 + p0] = tf32r(gelu(c[mm][nn][2] + bb0));
                    H1[(rr + 8)*264 + p1] = tf32r(gelu(c[mm][nn][3] + bb1));
                    #pragma unroll
                    for (int q = 0; q < 4; q++) c[mm][nn][q] = 0.f;
                }
            }
            __syncthreads();
        }
    }

    // epilogue-2: Y = c + b2 (row-major pitch 260, overlays H1 — all reads done)
    #pragma unroll
    for (int mm = 0; mm < 4; mm++){
        #pragma unroll
        for (int nn = 0; nn < 8; nn++){
            int rr = row0 + mm*16 + (lane >> 2);
            int cc = col0 + nn*8 + 2*(lane & 3);
            float bb0 = b2s[cc], bb1 = b2s[cc + 1];
            *(float2*)(Ysm + rr*260 + cc)       = make_float2(c[mm][nn][0] + bb0, c[mm][nn][1] + bb1);
            *(float2*)(Ysm + (rr + 8)*260 + cc) = make_float2(c[mm][nn][2] + bb0, c[mm][nn][3] + bb1);
        }
    }
    __syncthreads();

    // sorted-run segment accumulate: thread = column
    {
        int col = tid; float acc = 0.f; int cur = -1;
        for (int r = 0; r < 128; r++){
            int s = segs[r];
            if (s != cur){
                if (cur >= 0) atomicAdd(&g_segsum[(size_t)cur*256 + col], acc);
                acc = 0.f; cur = s;
            }
            if (s >= 0) acc += Ysm[r*260 + col];
        }
        if (cur >= 0) atomicAdd(&g_segsum[(size_t)cur*256 + col], acc);
    }
}

// ---------------------------------------------------------------------------
// head kernel: 128 groups/CTA, layer-1 tf32 mma (packed Wc1), final 256->10 FFMA
// ---------------------------------------------------------------------------
__device__ __forceinline__ void head_ldx(float* xr, const float* invc, int g0, int G, int c, int tid)
{
    int r = tid & 127, k8a = tid >> 7;
    int g = g0 + r;
    float iv = (g < G) ? invc[r] : 0.f;
    #pragma unroll
    for (int it = 0; it < 2; it++){
        int kg = c*32 + (k8a + it*2)*8;
        float4 v0 = make_float4(0.f,0.f,0.f,0.f), v1 = v0;
        if (g < G){
            v0 = *(const float4*)(g_segsum + (size_t)g*256 + kg);
            v1 = *(const float4*)(g_segsum + (size_t)g*256 + kg + 4);
            v0.x*=iv; v0.y*=iv; v0.z*=iv; v0.w*=iv;
            v1.x*=iv; v1.y*=iv; v1.z*=iv; v1.w*=iv;
        }
        float* x = xr + it*8;
        x[0]=v0.x; x[1]=v0.y; x[2]=v0.z; x[3]=v0.w;
        x[4]=v1.x; x[5]=v1.y; x[6]=v1.z; x[7]=v1.w;
    }
}

__global__ void __launch_bounds__(256, 1)
head_kernel(const float* __restrict__ bc1, const float* __restrict__ Wc2,
            const float* __restrict__ bc2, float* __restrict__ out, int G)
{
    extern __shared__ float smraw[];
    char* sb = (char*)smraw;
    uint32_t B0 = s2u(sb);
    float* Hs   = (float*)(sb + OFF_H1);    // row-major pitch 260 (epilogue overlay)
    float* w2s  = (float*)(sb + OFF_WF);    // 256 x 10
    float* bc1s = (float*)(sb + OFF_B1);
    float* bc2s = (float*)(sb + OFF_B2);
    float* invc = (float*)(sb + OFF_SEG);
    const uint32_t MB = B0 + OFF_MB;

    int tid = threadIdx.x, lane = tid & 31, warp = tid >> 5;
    int row0 = (warp & 1) * 64, cg = warp >> 1;
    int col0 = cg * 64;
    int g0 = blockIdx.x * 128;

    bc1s[tid] = bc1[tid];
    for (int i = tid; i < 2560; i += 256) w2s[i] = Wc2[i];
    if (tid < 16) bc2s[tid] = (tid < 10) ? bc2[tid] : 0.f;
    if (tid < 128){
        int g = g0 + tid;
        float cc = (g < G) ? g_segcnt[g] : 1.f;
        invc[tid] = 1.f / fmaxf(cc, 1.f);
    }
    if (tid == 0){ MB_INIT(MB, 1); MB_INIT(MB + 8, 1); }
    __syncthreads();

    float xr[16];
    head_ldx(xr, invc, g0, G, 0, tid);

    float c[4][8][4];
    #pragma unroll
    for (int mm = 0; mm < 4; mm++)
        #pragma unroll
        for (int nn = 0; nn < 8; nn++)
            #pragma unroll
            for (int q = 0; q < 4; q++) c[mm][nn][q] = 0.f;

    if (tid == 0){
        MB_EXPECT(MB, 32768u);
        bulkcp(B0 + OFF_H1, g_Wc1p, 32768, MB);
    }
    for (int gc = 0; gc < 8; gc++){
        int b = gc & 1;
        stage_stx(xr, (float*)(sb + (b ? OFF_X1 : OFF_X0)), tid);
        if (gc < 7) head_ldx(xr, invc, g0, G, gc + 1, tid);
        if (tid == 0 && gc < 7){
            int g2 = gc + 1, b2i = g2 & 1;
            MB_EXPECT(MB + b2i*8, 32768u);
            bulkcp(B0 + OFF_H1 + b2i*32768, g_Wc1p + g2*8192, 32768, MB + b2i*8);
        }
        __syncthreads();
        MB_WAIT(MB + b*8, (gc >> 1) & 1);
        const float* Wb = (const float*)(sb + OFF_H1 + b*32768);
        const float* Ab = (const float*)(sb + (b ? OFF_X1 : OFF_X0));
        #pragma unroll
        for (int k8 = 0; k8 < 4; k8++)
            kstep(Ab, 40, k8*8, Wb, k8, row0, cg, lane, c);
        __syncthreads();
    }

    // epilogue: Hs = gelu(c + bc1), fp32, pitch 260 (overlays W slots — reads done)
    #pragma unroll
    for (int mm = 0; mm < 4; mm++){
        #pragma unroll
        for (int nn = 0; nn < 8; nn++){
            int rr = row0 + mm*16 + (lane >> 2);
            int cc = col0 + nn*8 + 2*(lane & 3);
            float bb0 = bc1s[cc], bb1 = bc1s[cc + 1];
            *(float2*)(Hs + rr*260 + cc)       = make_float2(gelu(c[mm][nn][0] + bb0), gelu(c[mm][nn][1] + bb1));
            *(float2*)(Hs + (rr + 8)*260 + cc) = make_float2(gelu(c[mm][nn][2] + bb0), gelu(c[mm][nn][3] + bb1));
        }
    }
    __syncthreads();

    // final: out[128,10] = Hs[128,256] @ Wc2 + bc2 (FFMA)
    for (int i = tid; i < 1280; i += 256){
        int r = i / 10, cl = i - r*10;
        float acc = bc2s[cl];
        const float* hp = Hs + r*260;
        #pragma unroll 8
        for (int k = 0; k < 256; k++) acc += hp[k] * w2s[k*10 + cl];
        int g = g0 + r;
        if (g < G) out[(size_t)g*10 + cl] = acc;
    }
}

// ---------------------------------------------------------------------------
extern "C" void kernel_launch(void* const* d_in, const int* in_sizes, int n_in,
                              void* d_out, int out_size)
{
    const float* hf  = (const float*)d_in[0];
    const float* sf  = (const float*)d_in[1];
    const float* W1  = (const float*)d_in[2];
    const float* b1  = (const float*)d_in[3];
    const float* W2  = (const float*)d_in[4];
    const float* b2  = (const float*)d_in[5];
    const float* Wc1 = (const float*)d_in[6];
    const float* bc1 = (const float*)d_in[7];
    const float* Wc2 = (const float*)d_in[8];
    const float* bc2 = (const float*)d_in[9];
    const int*   seg = (const int*)d_in[10];

    int N = in_sizes[0] / 256;
    int G = out_size / 10;

    cudaFuncSetAttribute(node_kernel, cudaFuncAttributeMaxDynamicSharedMemorySize, SMB);
    cudaFuncSetAttribute(head_kernel, cudaFuncAttributeMaxDynamicSharedMemorySize, SMB);

    prep_kernel<<<2048, 256>>>(W1, W2, Wc1, seg, N, G);
    node_kernel<<<(N + 127) / 128, 256, SMB>>>(hf, sf, b1, b2, seg, N);
    head_kernel<<<(G + 127) / 128, 256, SMB>>>(bc1, Wc2, bc2, (float*)d_out, G);
}

// round 9
// speedup vs baseline: 1.5500x; 1.3666x over previous
#include <cuda_runtime.h>
#include <cuda_fp16.h>
#include <stdint.h>
#include <math.h>

#define GMAX 100000

// ---------------- static scratch ----------------
__device__ float  g_segsum[(size_t)GMAX*256];
__device__ float  g_segcnt[GMAX];
__device__ __half g_W1h[18*4096];   // fragment-packed fp16, K padded to 288
__device__ __half g_W2h[16*4096];
__device__ __half g_Wc1h[16*4096];

// ---------------- node smem layout (bytes) ----------------
// Y fp32 overlay [0,133120) contains: H1h fp16 [0,69632) (pitch 272 fp16),
//   L1-W slots [0,16384),[16384,32768), L2-W slots [69632,86016),[86016,102400),
//   X bufs [102400,114688),[114688,126976)
#define OFF_W2N  69632
#define OFF_XN   102400
#define OFF_B1N  133120
#define OFF_B2N  134144
#define OFF_SEGN 135168
#define OFF_MBN  135680
#define SMB_N    135744

// ---------------- head smem layout ----------------
// Hs fp32 overlay [0,135168) (pitch 264): W slots [0,32768), X [102400,126976)
#define OFF_W2SH 135168   // w2s 2560 f32
#define OFF_B1H  145408
#define OFF_B2H  146432
#define OFF_INVH 146560
#define OFF_MBH  147072
#define SMB_H    147456

__device__ __forceinline__ float gelu(float x){
    return 0.5f * x * (1.0f + erff(x * 0.70710678118654752f));
}
__device__ __forceinline__ void mma16(float* c, const unsigned* a, unsigned b0, unsigned b1){
    asm volatile(
        "mma.sync.aligned.m16n8k16.row.col.f32.f16.f16.f32 "
        "{%0,%1,%2,%3},{%4,%5,%6,%7},{%8,%9},{%0,%1,%2,%3};\n"
        : "+f"(c[0]), "+f"(c[1]), "+f"(c[2]), "+f"(c[3])
        : "r"(a[0]), "r"(a[1]), "r"(a[2]), "r"(a[3]), "r"(b0), "r"(b1));
}
__device__ __forceinline__ void bulkcp(uint32_t dst, const void* src, uint32_t bytes, uint32_t mbar){
    asm volatile("cp.async.bulk.shared::cluster.global.mbarrier::complete_tx::bytes [%0], [%1], %2, [%3];"
        :: "r"(dst), "l"(src), "r"(bytes), "r"(mbar) : "memory");
}
__device__ __forceinline__ uint32_t s2u(const void* p){
    uint32_t a; asm("{ .reg .u64 t; cvta.to.shared.u64 t, %1; cvt.u32.u64 %0, t; }" : "=r"(a) : "l"(p));
    return a;
}
#define MB_INIT(a,c)  asm volatile("mbarrier.init.shared.b64 [%0], %1;" :: "r"(a), "r"(c) : "memory")
#define MB_EXPECT(a,b) asm volatile("mbarrier.arrive.expect_tx.shared.b64 _, [%0], %1;" :: "r"(a), "r"(b) : "memory")
#define MB_WAIT(a,p) do{ uint32_t _m=(a); uint32_t _p=(p); uint32_t _d; \
    asm volatile("{\n\t.reg .pred p;\n\tmbarrier.try_wait.parity.acquire.cta.shared::cta.b64 p, [%1], %2;\n\tselp.b32 %0,1,0,p;\n\t}" \
        : "=r"(_d) : "r"(_m), "r"(_p) : "memory"); \
    if(!_d){ asm volatile("{\n\t.reg .pred P1;\nWL_%=:\n\tmbarrier.try_wait.parity.acquire.cta.shared::cta.b64 P1, [%0], %1, 0x989680;\n\t@P1 bra.uni WD_%=;\n\tbra.uni WL_%=;\nWD_%=:\n\t}" \
        :: "r"(_m), "r"(_p) : "memory"); } }while(0)

// ---------------------------------------------------------------------------
// prep: zero segsum, counts via binary search, fragment-pack weights (fp16)
// Flat pack: i = ((kk*16 + p)*32 + T)*8 + s*4 + reg*2 + half
//   n = (2p+s)*8 + (T>>2) ; k = kk*16 + (T&3)*2 + reg*8 + half
// ---------------------------------------------------------------------------
__device__ __forceinline__ void packWh(__half* dst, const float* src, int Ktrue, int nk16,
                                       size_t t0, size_t stride)
{
    size_t tot = (size_t)nk16 * 4096;
    for (size_t i = t0; i < tot; i += stride){
        int half = (int)(i & 1), reg = (int)((i >> 1) & 1), s = (int)((i >> 2) & 1);
        int T = (int)((i >> 3) & 31), p = (int)((i >> 8) & 15), kk = (int)(i >> 12);
        int n = (2*p + s)*8 + (T >> 2);
        int k = kk*16 + (T & 3)*2 + reg*8 + half;
        dst[i] = __float2half_rn((k < Ktrue) ? src[(size_t)k*256 + n] : 0.f);
    }
}

__global__ void prep_kernel(const float* __restrict__ W1, const float* __restrict__ W2,
                            const float* __restrict__ Wc1,
                            const int* __restrict__ seg, int N, int G)
{
    size_t stride = (size_t)gridDim.x * blockDim.x;
    size_t t0 = (size_t)blockIdx.x * blockDim.x + threadIdx.x;
    float4* z = (float4*)g_segsum;
    for (size_t i = t0; i < (size_t)G*64; i += stride) z[i] = make_float4(0.f,0.f,0.f,0.f);
    for (size_t g = t0; g < (size_t)G; g += stride){
        int gi = (int)g;
        int lo = 0, hi = N;
        while (lo < hi){ int m = (lo+hi) >> 1; if (seg[m] < gi) lo = m+1; else hi = m; }
        int lb = lo; hi = N;
        while (lo < hi){ int m = (lo+hi) >> 1; if (seg[m] <= gi) lo = m+1; else hi = m; }
        g_segcnt[g] = (float)(lo - lb);
    }
    packWh(g_W1h,  W1,  272, 18, t0, stride);
    packWh(g_W2h,  W2,  256, 16, t0, stride);
    packWh(g_Wc1h, Wc1, 256, 16, t0, stride);
}

// ---------------------------------------------------------------------------
// one k16 step for warp tile 64x64. A in smem fp16, pair-perm, pitch PA (fp16).
// W chunk base Wb (smem, fp16), step selects k16 within K=32 chunk.
// ---------------------------------------------------------------------------
__device__ __forceinline__ void kstep16(const __half* Ab, int PA, int k16off,
                                        const __half* Wb, int step, int cg,
                                        int row0, int lane, float c[4][8][4])
{
    unsigned a[4][4];
    #pragma unroll
    for (int mm = 0; mm < 4; mm++){
        int r = row0 + mm*16 + (lane >> 2);
        uint2 lo = *(const uint2*)(Ab + r*PA + k16off + (lane & 3)*4);
        uint2 hi = *(const uint2*)(Ab + (r + 8)*PA + k16off + (lane & 3)*4);
        a[mm][0] = lo.x; a[mm][1] = hi.x; a[mm][2] = lo.y; a[mm][3] = hi.y;
    }
    uint4 b[4];
    #pragma unroll
    for (int p = 0; p < 4; p++)
        b[p] = *(const uint4*)(Wb + step*4096 + ((cg*4 + p)*32 + lane)*8);
    #pragma unroll
    for (int mm = 0; mm < 4; mm++){
        #pragma unroll
        for (int p = 0; p < 4; p++){
            mma16(c[mm][p*2],     a[mm], b[p].x, b[p].y);
            mma16(c[mm][p*2 + 1], a[mm], b[p].z, b[p].w);
        }
    }
}

// X stage: 256 thr, row = tid&127, t2 = tid>>7 picks k16 half of a K=32 chunk.
__device__ __forceinline__ void x_from_f4(float* kv, const float4* v){
    kv[0]=v[0].x; kv[1]=v[0].y; kv[2]=v[0].z; kv[3]=v[0].w;
    kv[4]=v[1].x; kv[5]=v[1].y; kv[6]=v[1].z; kv[7]=v[1].w;
    kv[8]=v[2].x; kv[9]=v[2].y; kv[10]=v[2].z; kv[11]=v[2].w;
    kv[12]=v[3].x; kv[13]=v[3].y; kv[14]=v[3].z; kv[15]=v[3].w;
}
__device__ __forceinline__ void stage_stx(const float* kv, __half* xb, int tid)
{
    int r = tid & 127, t2 = tid >> 7;
    // pair perm: (0,1),(8,9),(2,3),(10,11),(4,5),(12,13),(6,7),(14,15)
    __half2 h[8];
    #pragma unroll
    for (int q = 0; q < 4; q++){
        h[q*2]     = __floats2half2_rn(kv[2*q],     kv[2*q + 1]);
        h[q*2 + 1] = __floats2half2_rn(kv[2*q + 8], kv[2*q + 9]);
    }
    uint32_t* d = (uint32_t*)(xb + r*48 + t2*16);
    asm volatile("st.shared.v4.b32 [%0], {%1,%2,%3,%4};" :: "l"(d),
        "r"(*(uint32_t*)&h[0]), "r"(*(uint32_t*)&h[1]), "r"(*(uint32_t*)&h[2]), "r"(*(uint32_t*)&h[3]) : "memory");
    asm volatile("st.shared.v4.b32 [%0], {%1,%2,%3,%4};" :: "l"(d + 4),
        "r"(*(uint32_t*)&h[4]), "r"(*(uint32_t*)&h[5]), "r"(*(uint32_t*)&h[6]), "r"(*(uint32_t*)&h[7]) : "memory");
}

__device__ __forceinline__ void node_ldx(float* kv, const float* hf, const float* sf,
                                         int r0, int N, int c, int tid)
{
    int r = tid & 127, t2 = tid >> 7;
    int gr = r0 + r, kg = c*32 + t2*16;
    float4 v[4];
    v[0]=v[1]=v[2]=v[3]=make_float4(0.f,0.f,0.f,0.f);
    if (gr < N){
        if (kg < 256){
            const float4* p = (const float4*)(hf + (size_t)gr*256 + kg);
            v[0]=p[0]; v[1]=p[1]; v[2]=p[2]; v[3]=p[3];
        } else if (kg < 272){
            const float4* p = (const float4*)(sf + (size_t)gr*16);
            v[0]=p[0]; v[1]=p[1]; v[2]=p[2]; v[3]=p[3];
        }
    }
    x_from_f4(kv, v);
}

// ---------------------------------------------------------------------------
// node kernel: 256 thr, 8 warps (2 row-groups x 4 col-groups), tile 128 rows
// gc 0..8: layer-1 (K=288, chunks of 32); gc 9..16: layer-2 (K=256)
// ---------------------------------------------------------------------------
__global__ void __launch_bounds__(256, 1)
node_kernel(const float* __restrict__ hf, const float* __restrict__ sf,
            const float* __restrict__ b1, const float* __restrict__ b2,
            const int* __restrict__ seg, int N)
{
    extern __shared__ float smraw[];
    char* sb = (char*)smraw;
    uint32_t B0 = s2u(sb);
    __half* H1h = (__half*)sb;              // pitch 272 fp16
    float*  Ysm = (float*)sb;               // pitch 260 fp32 (epilogue-2 overlay)
    float*  b1s = (float*)(sb + OFF_B1N);
    float*  b2s = (float*)(sb + OFF_B2N);
    int*   segs = (int*)(sb + OFF_SEGN);
    const uint32_t MB = B0 + OFF_MBN;

    int tid = threadIdx.x, lane = tid & 31, warp = tid >> 5;
    int row0 = (warp & 1) * 64, cg = warp >> 1;
    int col0 = cg * 64;
    int r0 = blockIdx.x * 128;

    b1s[tid] = b1[tid]; b2s[tid] = b2[tid];
    if (tid < 128){ int r = r0 + tid; segs[tid] = (r < N) ? seg[r] : -1; }
    if (tid == 0){ MB_INIT(MB, 1); MB_INIT(MB + 8, 1); }
    __syncthreads();

    float kv[16];
    node_ldx(kv, hf, sf, r0, N, 0, tid);

    float c[4][8][4];
    #pragma unroll
    for (int mm = 0; mm < 4; mm++)
        #pragma unroll
        for (int nn = 0; nn < 8; nn++)
            #pragma unroll
            for (int q = 0; q < 4; q++) c[mm][nn][q] = 0.f;

    if (tid == 0){  // kick chunk 0 -> L1 slot 0
        MB_EXPECT(MB, 16384u);
        bulkcp(B0, g_W1h, 16384, MB);
    }

    for (int gc = 0; gc < 17; gc++){
        int b = gc & 1;
        bool L1 = (gc < 9);
        if (L1){
            stage_stx(kv, (__half*)(sb + OFF_XN + b*12288), tid);
            if (gc < 8) node_ldx(kv, hf, sf, r0, N, gc + 1, tid);
        }
        if (tid == 0 && gc < 16){
            int g2 = gc + 1, b2i = g2 & 1;
            uint32_t slot = (g2 < 9) ? (B0 + b2i*16384) : (B0 + OFF_W2N + b2i*16384);
            const __half* src = (g2 < 9) ? (g_W1h + g2*8192) : (g_W2h + (g2 - 9)*8192);
            MB_EXPECT(MB + b2i*8, 16384u);
            bulkcp(slot, src, 16384, MB + b2i*8);
        }
        __syncthreads();
        MB_WAIT(MB + b*8, (gc >> 1) & 1);

        const __half* Wb = (const __half*)(sb + (L1 ? (b*16384) : (OFF_W2N + b*16384)));
        const __half* Ab = L1 ? (const __half*)(sb + OFF_XN + b*12288) : H1h;
        int PA = L1 ? 48 : 272;
        #pragma unroll
        for (int st = 0; st < 2; st++){
            int k16off = L1 ? (st*16) : (((gc - 9)*2 + st)*16);
            kstep16(Ab, PA, k16off, Wb, st, cg, row0, lane, c);
        }
        __syncthreads();

        if (gc == 8){
            // epilogue-1: H1h = fp16(gelu(c + b1)), pair-perm within k16 blocks
            #pragma unroll
            for (int mm = 0; mm < 4; mm++){
                #pragma unroll
                for (int nn = 0; nn < 8; nn++){
                    int rr = row0 + mm*16 + (lane >> 2);
                    int cc = col0 + nn*8 + 2*(lane & 3);
                    int pos = (cc >> 4)*16 + ((cc & 7) >> 1)*4 + ((cc >> 3) & 1)*2;
                    float bb0 = b1s[cc], bb1 = b1s[cc + 1];
                    *(__half2*)(H1h + rr*272 + pos) =
                        __floats2half2_rn(gelu(c[mm][nn][0] + bb0), gelu(c[mm][nn][1] + bb1));
                    *(__half2*)(H1h + (rr + 8)*272 + pos) =
                        __floats2half2_rn(gelu(c[mm][nn][2] + bb0), gelu(c[mm][nn][3] + bb1));
                    #pragma unroll
                    for (int q = 0; q < 4; q++) c[mm][nn][q] = 0.f;
                }
            }
            __syncthreads();
        }
    }

    // epilogue-2: Y = c + b2 (fp32, pitch 260, overlays everything — reads done)
    #pragma unroll
    for (int mm = 0; mm < 4; mm++){
        #pragma unroll
        for (int nn = 0; nn < 8; nn++){
            int rr = row0 + mm*16 + (lane >> 2);
            int cc = col0 + nn*8 + 2*(lane & 3);
            float bb0 = b2s[cc], bb1 = b2s[cc + 1];
            *(float2*)(Ysm + rr*260 + cc)       = make_float2(c[mm][nn][0] + bb0, c[mm][nn][1] + bb1);
            *(float2*)(Ysm + (rr + 8)*260 + cc) = make_float2(c[mm][nn][2] + bb0, c[mm][nn][3] + bb1);
        }
    }
    __syncthreads();

    // sorted-run segment accumulate: thread = column
    {
        int col = tid; float acc = 0.f; int cur = -1;
        for (int r = 0; r < 128; r++){
            int s = segs[r];
            if (s != cur){
                if (cur >= 0) atomicAdd(&g_segsum[(size_t)cur*256 + col], acc);
                acc = 0.f; cur = s;
            }
            if (s >= 0) acc += Ysm[r*260 + col];
        }
        if (cur >= 0) atomicAdd(&g_segsum[(size_t)cur*256 + col], acc);
    }
}

// ---------------------------------------------------------------------------
// head kernel: 128 groups/CTA; layer-1 fp16 mma; final 256->10 FFMA
// ---------------------------------------------------------------------------
__device__ __forceinline__ void head_ldx(float* kv, const float* invc, int g0, int G, int c, int tid)
{
    int r = tid & 127, t2 = tid >> 7;
    int g = g0 + r, kg = c*32 + t2*16;
    float4 v[4];
    v[0]=v[1]=v[2]=v[3]=make_float4(0.f,0.f,0.f,0.f);
    if (g < G){
        const float4* p = (const float4*)(g_segsum + (size_t)g*256 + kg);
        float iv = invc[r];
        #pragma unroll
        for (int q = 0; q < 4; q++){
            float4 t = p[q];
            v[q] = make_float4(t.x*iv, t.y*iv, t.z*iv, t.w*iv);
        }
    }
    x_from_f4(kv, v);
}

__global__ void __launch_bounds__(256, 1)
head_kernel(const float* __restrict__ bc1, const float* __restrict__ Wc2,
            const float* __restrict__ bc2, float* __restrict__ out, int G)
{
    extern __shared__ float smraw[];
    char* sb = (char*)smraw;
    uint32_t B0 = s2u(sb);
    float* Hs   = (float*)sb;               // pitch 264 fp32 (epilogue overlay)
    float* w2s  = (float*)(sb + OFF_W2SH);  // 256 x 10
    float* bc1s = (float*)(sb + OFF_B1H);
    float* bc2s = (float*)(sb + OFF_B2H);
    float* invc = (float*)(sb + OFF_INVH);
    const uint32_t MB = B0 + OFF_MBH;

    int tid = threadIdx.x, lane = tid & 31, warp = tid >> 5;
    int row0 = (warp & 1) * 64, cg = warp >> 1;
    int col0 = cg * 64;
    int g0 = blockIdx.x * 128;

    bc1s[tid] = bc1[tid];
    for (int i = tid; i < 2560; i += 256) w2s[i] = Wc2[i];
    if (tid < 16) bc2s[tid] = (tid < 10) ? bc2[tid] : 0.f;
    if (tid < 128){
        int g = g0 + tid;
        float cc = (g < G) ? g_segcnt[g] : 1.f;
        invc[tid] = 1.f / fmaxf(cc, 1.f);
    }
    if (tid == 0){ MB_INIT(MB, 1); MB_INIT(MB + 8, 1); }
    __syncthreads();

    float kv[16];
    head_ldx(kv, invc, g0, G, 0, tid);

    float c[4][8][4];
    #pragma unroll
    for (int mm = 0; mm < 4; mm++)
        #pragma unroll
        for (int nn = 0; nn < 8; nn++)
            #pragma unroll
            for (int q = 0; q < 4; q++) c[mm][nn][q] = 0.f;

    if (tid == 0){
        MB_EXPECT(MB, 16384u);
        bulkcp(B0, g_Wc1h, 16384, MB);
    }
    for (int gc = 0; gc < 8; gc++){
        int b = gc & 1;
        stage_stx(kv, (__half*)(sb + OFF_XN + b*12288), tid);
        if (gc < 7) head_ldx(kv, invc, g0, G, gc + 1, tid);
        if (tid == 0 && gc < 7){
            int g2 = gc + 1, b2i = g2 & 1;
            MB_EXPECT(MB + b2i*8, 16384u);
            bulkcp(B0 + b2i*16384, g_Wc1h + g2*8192, 16384, MB + b2i*8);
        }
        __syncthreads();
        MB_WAIT(MB + b*8, (gc >> 1) & 1);
        const __half* Wb = (const __half*)(sb + b*16384);
        const __half* Ab = (const __half*)(sb + OFF_XN + b*12288);
        #pragma unroll
        for (int st = 0; st < 2; st++)
            kstep16(Ab, 48, st*16, Wb, st, cg, row0, lane, c);
        __syncthreads();
    }

    // epilogue: Hs = gelu(c + bc1), fp32, pitch 264 (overlay — reads done)
    #pragma unroll
    for (int mm = 0; mm < 4; mm++){
        #pragma unroll
        for (int nn = 0; nn < 8; nn++){
            int rr = row0 + mm*16 + (lane >> 2);
            int cc = col0 + nn*8 + 2*(lane & 3);
            float bb0 = bc1s[cc], bb1 = bc1s[cc + 1];
            *(float2*)(Hs + rr*264 + cc)       = make_float2(gelu(c[mm][nn][0] + bb0), gelu(c[mm][nn][1] + bb1));
            *(float2*)(Hs + (rr + 8)*264 + cc) = make_float2(gelu(c[mm][nn][2] + bb0), gelu(c[mm][nn][3] + bb1));
        }
    }
    __syncthreads();

    // final: out[128,10] = Hs[128,256] @ Wc2 + bc2 (FFMA)
    for (int i = tid; i < 1280; i += 256){
        int r = i / 10, cl = i - r*10;
        float acc = bc2s[cl];
        const float* hp = Hs + r*264;
        #pragma unroll 8
        for (int k = 0; k < 256; k++) acc += hp[k] * w2s[k*10 + cl];
        int g = g0 + r;
        if (g < G) out[(size_t)g*10 + cl] = acc;
    }
}

// ---------------------------------------------------------------------------
extern "C" void kernel_launch(void* const* d_in, const int* in_sizes, int n_in,
                              void* d_out, int out_size)
{
    const float* hf  = (const float*)d_in[0];
    const float* sf  = (const float*)d_in[1];
    const float* W1  = (const float*)d_in[2];
    const float* b1  = (const float*)d_in[3];
    const float* W2  = (const float*)d_in[4];
    const float* b2  = (const float*)d_in[5];
    const float* Wc1 = (const float*)d_in[6];
    const float* bc1 = (const float*)d_in[7];
    const float* Wc2 = (const float*)d_in[8];
    const float* bc2 = (const float*)d_in[9];
    const int*   seg = (const int*)d_in[10];

    int N = in_sizes[0] / 256;
    int G = out_size / 10;

    cudaFuncSetAttribute(node_kernel, cudaFuncAttributeMaxDynamicSharedMemorySize, SMB_N);
    cudaFuncSetAttribute(head_kernel, cudaFuncAttributeMaxDynamicSharedMemorySize, SMB_H);

    prep_kernel<<<2048, 256>>>(W1, W2, Wc1, seg, N, G);
    node_kernel<<<(N + 127) / 128, 256, SMB_N>>>(hf, sf, b1, b2, seg, N);
    head_kernel<<<(G + 127) / 128, 256, SMB_H>>>(bc1, Wc2, bc2, (float*)d_out, G);
}

// round 13
// speedup vs baseline: 1.6962x; 1.0943x over previous
#include <cuda_runtime.h>
#include <cuda_fp16.h>
#include <stdint.h>
#include <math.h>

#define GMAX 100000

// ---------------- static scratch ----------------
__device__ float  g_segsum[(size_t)GMAX*256];
__device__ float  g_segcnt[GMAX];
__device__ __half g_W1h[18*4096];   // fragment-packed fp16, K padded to 288 (18 k16-blocks)
__device__ __half g_W2h[16*4096];
__device__ __half g_Wc1h[16*4096];

// ---------------- node smem (bytes) ----------------
// [0,65536)        W slots 2 x 32KB (K=64 chunks)
// [65536,131072)   H1h blocked: 16 blks x (128 rows x 16 fp16) = 64KB
// [131072,163840)  X bufs 2 x 16KB (4 blks each)
// Y fp32 overlay [0,133120) pitch 260 — epilogue-2 only
#define NOFF_H1   65536
#define NOFF_X    131072
#define NOFF_B1   163840
#define NOFF_B2   164864
#define NOFF_SEG  165888
#define NOFF_MB   166400
#define SMB_N     166464

// ---------------- head smem ----------------
// [0,32768) W slots 2x16KB ; [32768,49152) X bufs 2x8KB
// Hs fp32 overlay [0,135168) pitch 264
#define HOFF_X    32768
#define HOFF_W2S  135168
#define HOFF_B1   145408
#define HOFF_B2   146432
#define HOFF_INV  146496
#define HOFF_MB   147008
#define SMB_H     147456

__device__ __forceinline__ float gelu(float x){
    return 0.5f * x * (1.0f + erff(x * 0.70710678118654752f));
}
__device__ __forceinline__ void mma16(float* c, const unsigned* a, unsigned b0, unsigned b1){
    asm volatile(
        "mma.sync.aligned.m16n8k16.row.col.f32.f16.f16.f32 "
        "{%0,%1,%2,%3},{%4,%5,%6,%7},{%8,%9},{%0,%1,%2,%3};\n"
        : "+f"(c[0]), "+f"(c[1]), "+f"(c[2]), "+f"(c[3])
        : "r"(a[0]), "r"(a[1]), "r"(a[2]), "r"(a[3]), "r"(b0), "r"(b1));
}
__device__ __forceinline__ void bulkcp(uint32_t dst, const void* src, uint32_t bytes, uint32_t mbar){
    asm volatile("cp.async.bulk.shared::cluster.global.mbarrier::complete_tx::bytes [%0], [%1], %2, [%3];"
        :: "r"(dst), "l"(src), "r"(bytes), "r"(mbar) : "memory");
}
__device__ __forceinline__ uint32_t s2u(const void* p){
    uint32_t a; asm("{ .reg .u64 t; cvta.to.shared.u64 t, %1; cvt.u32.u64 %0, t; }" : "=r"(a) : "l"(p));
    return a;
}
#define MB_INIT(a,c)  asm volatile("mbarrier.init.shared.b64 [%0], %1;" :: "r"(a), "r"(c) : "memory")
#define MB_EXPECT(a,b) asm volatile("mbarrier.arrive.expect_tx.shared.b64 _, [%0], %1;" :: "r"(a), "r"(b) : "memory")
#define FEN_ASYNC()   asm volatile("fence.proxy.async.shared::cta;" ::: "memory")
#define MB_WAIT(a,p) do{ uint32_t _m=(a); uint32_t _p=(p); uint32_t _d; \
    asm volatile("{\n\t.reg .pred p;\n\tmbarrier.try_wait.parity.acquire.cta.shared::cta.b64 p, [%1], %2;\n\tselp.b32 %0,1,0,p;\n\t}" \
        : "=r"(_d) : "r"(_m), "r"(_p) : "memory"); \
    if(!_d){ asm volatile("{\n\t.reg .pred P1;\nWL_%=:\n\tmbarrier.try_wait.parity.acquire.cta.shared::cta.b64 P1, [%0], %1, 0x989680;\n\t@P1 bra.uni WD_%=;\n\tbra.uni WL_%=;\nWD_%=:\n\t}" \
        :: "r"(_m), "r"(_p) : "memory"); } }while(0)

// ---------------------------------------------------------------------------
// prep: zero segsum, counts via binary search, fragment-pack weights (fp16)
// pack index: i = ((kk*16 + p)*32 + T)*8 + s*4 + reg*2 + half
//   n = (2p+s)*8 + (T>>2) ; k = kk*16 + (T&3)*2 + reg*8 + half
// ---------------------------------------------------------------------------
__device__ __forceinline__ void packWh(__half* dst, const float* src, int Ktrue, int nk16,
                                       size_t t0, size_t stride)
{
    size_t tot = (size_t)nk16 * 4096;
    for (size_t i = t0; i < tot; i += stride){
        int half = (int)(i & 1), reg = (int)((i >> 1) & 1), s = (int)((i >> 2) & 1);
        int T = (int)((i >> 3) & 31), p = (int)((i >> 8) & 15), kk = (int)(i >> 12);
        int n = (2*p + s)*8 + (T >> 2);
        int k = kk*16 + (T & 3)*2 + reg*8 + half;
        dst[i] = __float2half_rn((k < Ktrue) ? src[(size_t)k*256 + n] : 0.f);
    }
}

__global__ void prep_kernel(const float* __restrict__ W1, const float* __restrict__ W2,
                            const float* __restrict__ Wc1,
                            const int* __restrict__ seg, int N, int G)
{
    size_t stride = (size_t)gridDim.x * blockDim.x;
    size_t t0 = (size_t)blockIdx.x * blockDim.x + threadIdx.x;
    float4* z = (float4*)g_segsum;
    for (size_t i = t0; i < (size_t)G*64; i += stride) z[i] = make_float4(0.f,0.f,0.f,0.f);
    for (size_t g = t0; g < (size_t)G; g += stride){
        int gi = (int)g;
        int lo = 0, hi = N;
        while (lo < hi){ int m = (lo+hi) >> 1; if (seg[m] < gi) lo = m+1; else hi = m; }
        int lb = lo; hi = N;
        while (lo < hi){ int m = (lo+hi) >> 1; if (seg[m] <= gi) lo = m+1; else hi = m; }
        g_segcnt[g] = (float)(lo - lb);
    }
    packWh(g_W1h,  W1,  272, 18, t0, stride);
    packWh(g_W2h,  W2,  256, 16, t0, stride);
    packWh(g_Wc1h, Wc1, 256, 16, t0, stride);
}

// ---------------------------------------------------------------------------
// one k16 step, warp tile 64x64. A blocked: Ab[blk][128][16] fp16, pair-perm.
// ---------------------------------------------------------------------------
__device__ __forceinline__ void kstep16b(const __half* Ab, int blk, const __half* Wb, int step,
                                         int cg, int row0, int lane, float c[4][8][4])
{
    const __half* Abase = Ab + (size_t)blk*2048;  // 128*16
    unsigned a[4][4];
    #pragma unroll
    for (int mm = 0; mm < 4; mm++){
        int r = row0 + mm*16 + (lane >> 2);
        uint2 lo = *(const uint2*)(Abase + r*16 + (lane & 3)*4);
        uint2 hi = *(const uint2*)(Abase + (r + 8)*16 + (lane & 3)*4);
        a[mm][0] = lo.x; a[mm][1] = hi.x; a[mm][2] = lo.y; a[mm][3] = hi.y;
    }
    uint4 b[4];
    #pragma unroll
    for (int p = 0; p < 4; p++)
        b[p] = *(const uint4*)(Wb + step*4096 + ((cg*4 + p)*32 + lane)*8);
    #pragma unroll
    for (int mm = 0; mm < 4; mm++){
        #pragma unroll
        for (int p = 0; p < 4; p++){
            mma16(c[mm][p*2],     a[mm], b[p].x, b[p].y);
            mma16(c[mm][p*2 + 1], a[mm], b[p].z, b[p].w);
        }
    }
}

// pair-perm 16 fp32 -> 16 fp16 at dst: (0,1),(8,9),(2,3),(10,11),(4,5),(12,13),(6,7),(14,15)
__device__ __forceinline__ void stage_blk16(const float* v, __half* dst)
{
    __half2 h[8];
    #pragma unroll
    for (int q = 0; q < 4; q++){
        h[q*2]     = __floats2half2_rn(v[2*q],     v[2*q + 1]);
        h[q*2 + 1] = __floats2half2_rn(v[2*q + 8], v[2*q + 9]);
    }
    uint32_t* d = (uint32_t*)dst;
    asm volatile("st.shared.v4.b32 [%0], {%1,%2,%3,%4};" :: "l"(d),
        "r"(*(uint32_t*)&h[0]), "r"(*(uint32_t*)&h[1]), "r"(*(uint32_t*)&h[2]), "r"(*(uint32_t*)&h[3]) : "memory");
    asm volatile("st.shared.v4.b32 [%0], {%1,%2,%3,%4};" :: "l"(d + 4),
        "r"(*(uint32_t*)&h[4]), "r"(*(uint32_t*)&h[5]), "r"(*(uint32_t*)&h[6]), "r"(*(uint32_t*)&h[7]) : "memory");
}

// ---------------------------------------------------------------------------
// node kernel: 256 thr, 8 warps (2 row x 4 col groups), 128-row tile
// 9 rounds: 0..4 layer-1 (K=64,64,64,64,32), 5..8 layer-2 (K=64 each)
// ---------------------------------------------------------------------------
__device__ __forceinline__ void node_ldx64(float* kv, const float* hf, const float* sf,
                                           int r0, int N, int rc, int tid)
{
    int r = tid & 127, t2 = tid >> 7;
    int gr = r0 + r, kg = rc*64 + t2*32;
    float4 v[8];
    #pragma unroll
    for (int q = 0; q < 8; q++) v[q] = make_float4(0.f,0.f,0.f,0.f);
    if (gr < N){
        if (kg < 256){
            const float4* p = (const float4*)(hf + (size_t)gr*256 + kg);
            #pragma unroll
            for (int q = 0; q < 8; q++) v[q] = p[q];
        } else if (kg < 272){
            const float4* p = (const float4*)(sf + (size_t)gr*16);
            #pragma unroll
            for (int q = 0; q < 4; q++) v[q] = p[q];
        }
    }
    #pragma unroll
    for (int q = 0; q < 8; q++){
        kv[q*4+0]=v[q].x; kv[q*4+1]=v[q].y; kv[q*4+2]=v[q].z; kv[q*4+3]=v[q].w;
    }
}
__device__ __forceinline__ void stage64(const float* kv, __half* xb, int tid)
{
    int r = tid & 127, t2 = tid >> 7;
    stage_blk16(kv,      xb + ((size_t)(2*t2)*128 + r)*16);
    stage_blk16(kv + 16, xb + ((size_t)(2*t2+1)*128 + r)*16);
}

__global__ void __launch_bounds__(256, 1)
node_kernel(const float* __restrict__ hf, const float* __restrict__ sf,
            const float* __restrict__ b1, const float* __restrict__ b2,
            const int* __restrict__ seg, int N)
{
    extern __shared__ float smraw[];
    char* sb = (char*)smraw;
    uint32_t B0 = s2u(sb);
    __half* H1h = (__half*)(sb + NOFF_H1);
    float*  Ysm = (float*)sb;
    float*  b1s = (float*)(sb + NOFF_B1);
    float*  b2s = (float*)(sb + NOFF_B2);
    int*   segs = (int*)(sb + NOFF_SEG);
    const uint32_t MB = B0 + NOFF_MB;

    int tid = threadIdx.x, lane = tid & 31, warp = tid >> 5;
    int row0 = (warp & 1) * 64, cg = warp >> 1;
    int col0 = cg * 64;
    int r0 = blockIdx.x * 128;

    b1s[tid] = b1[tid]; b2s[tid] = b2[tid];
    if (tid < 128){ int r = r0 + tid; segs[tid] = (r < N) ? seg[r] : -1; }
    if (tid == 0){
        MB_INIT(MB, 1); MB_INIT(MB + 8, 1);
        FEN_ASYNC();
        MB_EXPECT(MB, 32768u);
        bulkcp(B0, g_W1h, 32768, MB);          // chunk 0 -> slot 0
    }
    __syncthreads();

    float kv[32];
    node_ldx64(kv, hf, sf, r0, N, 0, tid);

    float c[4][8][4];
    #pragma unroll
    for (int mm = 0; mm < 4; mm++)
        #pragma unroll
        for (int nn = 0; nn < 8; nn++)
            #pragma unroll
            for (int q = 0; q < 4; q++) c[mm][nn][q] = 0.f;

    for (int rc = 0; rc < 9; rc++){
        int b = rc & 1;
        bool L1 = (rc < 5);
        if (L1){
            stage64(kv, (__half*)(sb + NOFF_X + b*16384), tid);
            if (rc < 4) node_ldx64(kv, hf, sf, r0, N, rc + 1, tid);
        }
        __syncthreads();   // all warps done with: compute(rc-1) [slot nb free], X buf b reads of rc-2
        if (tid == 0 && rc < 8){
            int nc = rc + 1, nb = nc & 1;
            uint32_t bytes = (nc == 4) ? 16384u : 32768u;
            const __half* src = (nc < 5) ? (g_W1h + nc*16384) : (g_W2h + (nc - 5)*16384);
            MB_EXPECT(MB + nb*8, bytes);
            bulkcp(B0 + nb*32768, src, bytes, MB + nb*8);
        }
        MB_WAIT(MB + b*8, (rc >> 1) & 1);
        const __half* Wb = (const __half*)(sb + b*32768);
        if (L1){
            const __half* Ab = (const __half*)(sb + NOFF_X + b*16384);
            kstep16b(Ab, 0, Wb, 0, cg, row0, lane, c);
            kstep16b(Ab, 1, Wb, 1, cg, row0, lane, c);
            if (rc != 4){
                kstep16b(Ab, 2, Wb, 2, cg, row0, lane, c);
                kstep16b(Ab, 3, Wb, 3, cg, row0, lane, c);
            }
        } else {
            int kb = (rc - 5)*4;
            kstep16b(H1h, kb + 0, Wb, 0, cg, row0, lane, c);
            kstep16b(H1h, kb + 1, Wb, 1, cg, row0, lane, c);
            kstep16b(H1h, kb + 2, Wb, 2, cg, row0, lane, c);
            kstep16b(H1h, kb + 3, Wb, 3, cg, row0, lane, c);
        }

        if (rc == 4){
            __syncthreads();   // all X reads done before H1 writes (regions disjoint, but keep ordered)
            // epilogue-1: H1h = fp16(gelu(c + b1)), blocked pair-perm layout
            #pragma unroll
            for (int mm = 0; mm < 4; mm++){
                #pragma unroll
                for (int nn = 0; nn < 8; nn++){
                    int rr = row0 + mm*16 + (lane >> 2);
                    int cc = col0 + nn*8 + 2*(lane & 3);
                    int blk = cc >> 4;
                    int pos = ((cc & 7) >> 1)*4 + ((cc >> 3) & 1)*2;
                    __half* p0 = H1h + ((size_t)blk*128 + rr)*16 + pos;
                    float bb0 = b1s[cc], bb1 = b1s[cc + 1];
                    *(__half2*)p0         = __floats2half2_rn(gelu(c[mm][nn][0] + bb0), gelu(c[mm][nn][1] + bb1));
                    *(__half2*)(p0 + 128) = __floats2half2_rn(gelu(c[mm][nn][2] + bb0), gelu(c[mm][nn][3] + bb1));
                    #pragma unroll
                    for (int q = 0; q < 4; q++) c[mm][nn][q] = 0.f;
                }
            }
            // round 5's leading __syncthreads orders these writes before H1 reads
        }
    }
    __syncthreads();

    // epilogue-2: Y = c + b2 (fp32, pitch 260, overlays W slots + H1 — reads done)
    #pragma unroll
    for (int mm = 0; mm < 4; mm++){
        #pragma unroll
        for (int nn = 0; nn < 8; nn++){
            int rr = row0 + mm*16 + (lane >> 2);
            int cc = col0 + nn*8 + 2*(lane & 3);
            float bb0 = b2s[cc], bb1 = b2s[cc + 1];
            *(float2*)(Ysm + rr*260 + cc)       = make_float2(c[mm][nn][0] + bb0, c[mm][nn][1] + bb1);
            *(float2*)(Ysm + (rr + 8)*260 + cc) = make_float2(c[mm][nn][2] + bb0, c[mm][nn][3] + bb1);
        }
    }
    __syncthreads();

    // sorted-run segment accumulate: thread = column
    {
        int col = tid; float acc = 0.f; int cur = -1;
        for (int r = 0; r < 128; r++){
            int s = segs[r];
            if (s != cur){
                if (cur >= 0) atomicAdd(&g_segsum[(size_t)cur*256 + col], acc);
                acc = 0.f; cur = s;
            }
            if (s >= 0) acc += Ysm[r*260 + col];
        }
        if (cur >= 0) atomicAdd(&g_segsum[(size_t)cur*256 + col], acc);
    }
}

// ---------------------------------------------------------------------------
// head kernel: 128 groups/CTA, 8 rounds of K=32; final 256->10 FFMA
// ---------------------------------------------------------------------------
__device__ __forceinline__ void head_ldx32(float* kv, const float* invc, int g0, int G, int rc, int tid)
{
    int r = tid & 127, t2 = tid >> 7;
    int g = g0 + r, kg = rc*32 + t2*16;
    float4 v[4];
    #pragma unroll
    for (int q = 0; q < 4; q++) v[q] = make_float4(0.f,0.f,0.f,0.f);
    if (g < G){
        const float4* p = (const float4*)(g_segsum + (size_t)g*256 + kg);
        float iv = invc[r];
        #pragma unroll
        for (int q = 0; q < 4; q++){
            float4 t = p[q];
            v[q] = make_float4(t.x*iv, t.y*iv, t.z*iv, t.w*iv);
        }
    }
    #pragma unroll
    for (int q = 0; q < 4; q++){
        kv[q*4+0]=v[q].x; kv[q*4+1]=v[q].y; kv[q*4+2]=v[q].z; kv[q*4+3]=v[q].w;
    }
}

__global__ void __launch_bounds__(256, 1)
head_kernel(const float* __restrict__ bc1, const float* __restrict__ Wc2,
            const float* __restrict__ bc2, float* __restrict__ out, int G)
{
    extern __shared__ float smraw[];
    char* sb = (char*)smraw;
    uint32_t B0 = s2u(sb);
    float* Hs   = (float*)sb;               // pitch 264 fp32 overlay
    float* w2s  = (float*)(sb + HOFF_W2S);
    float* bc1s = (float*)(sb + HOFF_B1);
    float* bc2s = (float*)(sb + HOFF_B2);
    float* invc = (float*)(sb + HOFF_INV);
    const uint32_t MB = B0 + HOFF_MB;

    int tid = threadIdx.x, lane = tid & 31, warp = tid >> 5;
    int row0 = (warp & 1) * 64, cg = warp >> 1;
    int col0 = cg * 64;
    int g0 = blockIdx.x * 128;

    bc1s[tid] = bc1[tid];
    for (int i = tid; i < 2560; i += 256) w2s[i] = Wc2[i];
    if (tid < 16) bc2s[tid] = (tid < 10) ? bc2[tid] : 0.f;
    if (tid < 128){
        int g = g0 + tid;
        float cc = (g < G) ? g_segcnt[g] : 1.f;
        invc[tid] = 1.f / fmaxf(cc, 1.f);
    }
    if (tid == 0){
        MB_INIT(MB, 1); MB_INIT(MB + 8, 1);
        FEN_ASYNC();
        MB_EXPECT(MB, 16384u);
        bulkcp(B0, g_Wc1h, 16384, MB);
    }
    __syncthreads();

    float kv[16];
    head_ldx32(kv, invc, g0, G, 0, tid);

    float c[4][8][4];
    #pragma unroll
    for (int mm = 0; mm < 4; mm++)
        #pragma unroll
        for (int nn = 0; nn < 8; nn++)
            #pragma unroll
            for (int q = 0; q < 4; q++) c[mm][nn][q] = 0.f;

    for (int rc = 0; rc < 8; rc++){
        int b = rc & 1;
        {
            int r = tid & 127, t2 = tid >> 7;
            stage_blk16(kv, (__half*)(sb + HOFF_X + b*8192) + ((size_t)t2*128 + r)*16);
        }
        if (rc < 7) head_ldx32(kv, invc, g0, G, rc + 1, tid);
        __syncthreads();
        if (tid == 0 && rc < 7){
            int nc = rc + 1, nb = nc & 1;
            MB_EXPECT(MB + nb*8, 16384u);
            bulkcp(B0 + nb*16384, g_Wc1h + nc*8192, 16384, MB + nb*8);
        }
        MB_WAIT(MB + b*8, (rc >> 1) & 1);
        const __half* Wb = (const __half*)(sb + b*16384);
        const __half* Ab = (const __half*)(sb + HOFF_X + b*8192);
        kstep16b(Ab, 0, Wb, 0, cg, row0, lane, c);
        kstep16b(Ab, 1, Wb, 1, cg, row0, lane, c);
    }
    __syncthreads();

    // epilogue: Hs = gelu(c + bc1), fp32, pitch 264 (overlay — reads done)
    #pragma unroll
    for (int mm = 0; mm < 4; mm++){
        #pragma unroll
        for (int nn = 0; nn < 8; nn++){
            int rr = row0 + mm*16 + (lane >> 2);
            int cc = col0 + nn*8 + 2*(lane & 3);
            float bb0 = bc1s[cc], bb1 = bc1s[cc + 1];
            *(float2*)(Hs + rr*264 + cc)       = make_float2(gelu(c[mm][nn][0] + bb0), gelu(c[mm][nn][1] + bb1));
            *(float2*)(Hs + (rr + 8)*264 + cc) = make_float2(gelu(c[mm][nn][2] + bb0), gelu(c[mm][nn][3] + bb1));
        }
    }
    __syncthreads();

    // final: out[128,10] = Hs[128,256] @ Wc2 + bc2 (FFMA)
    for (int i = tid; i < 1280; i += 256){
        int r = i / 10, cl = i - r*10;
        float acc = bc2s[cl];
        const float* hp = Hs + r*264;
        #pragma unroll 8
        for (int k = 0; k < 256; k++) acc += hp[k] * w2s[k*10 + cl];
        int g = g0 + r;
        if (g < G) out[(size_t)g*10 + cl] = acc;
    }
}

// ---------------------------------------------------------------------------
extern "C" void kernel_launch(void* const* d_in, const int* in_sizes, int n_in,
                              void* d_out, int out_size)
{
    const float* hf  = (const float*)d_in[0];
    const float* sf  = (const float*)d_in[1];
    const float* W1  = (const float*)d_in[2];
    const float* b1  = (const float*)d_in[3];
    const float* W2  = (const float*)d_in[4];
    const float* b2  = (const float*)d_in[5];
    const float* Wc1 = (const float*)d_in[6];
    const float* bc1 = (const float*)d_in[7];
    const float* Wc2 = (const float*)d_in[8];
    const float* bc2 = (const float*)d_in[9];
    const int*   seg = (const int*)d_in[10];

    int N = in_sizes[0] / 256;
    int G = out_size / 10;

    cudaFuncSetAttribute(node_kernel, cudaFuncAttributeMaxDynamicSharedMemorySize, SMB_N);
    cudaFuncSetAttribute(head_kernel, cudaFuncAttributeMaxDynamicSharedMemorySize, SMB_H);

    prep_kernel<<<2048, 256>>>(W1, W2, Wc1, seg, N, G);
    node_kernel<<<(N + 127) / 128, 256, SMB_N>>>(hf, sf, b1, b2, seg, N);
    head_kernel<<<(G + 127) / 128, 256, SMB_H>>>(bc1, Wc2, bc2, (float*)d_out, G);
}